// round 15
// baseline (speedup 1.0000x reference)
#include <cuda_runtime.h>
#include <cuda_fp16.h>
#include <cstddef>
#include <cstdint>

#define Bn 32
#define Tn 256
#define Wn 128
#define Rn 4
#define Nn 128
#define IFACEn 919
#define NTH 1024
#define DELTAf 1e-6f

typedef unsigned long long ull;

// -------- transposed-weight scratch + pipeline buffers (device globals) --------
__device__ float  g_encT[256 * 512];    // [k][j] fp32 (encoder, latency-hidden)
__device__ float  g_cpreT[128 * 512];   // [k][j] fp32
__device__ __half g_cboH[640 * 640];    // [k][j] fp16: k = rv(512)||h(128); j = gates(512)||out(128)
__device__ __half g_ifcH[128 * 920];    // [k][j] fp16, j padded 919->920
__device__ float  g_benc[512];
__device__ float  g_bctl[512];
__device__ float  g_bifc[920];
__device__ float  g_bout[128];
__device__ float  g_ctlpre[(size_t)Bn * Tn * 1024];
__device__ int    g_prog[2 * Bn];

__global__ void prep_kernel(
    const float* __restrict__ enc_Wih, const float* __restrict__ enc_Whh,
    const float* __restrict__ enc_bih, const float* __restrict__ enc_bhh,
    const float* __restrict__ ctl_Wih, const float* __restrict__ ctl_Whh,
    const float* __restrict__ ctl_bih, const float* __restrict__ ctl_bhh,
    const float* __restrict__ iface_W, const float* __restrict__ iface_b,
    const float* __restrict__ out_W, const float* __restrict__ out_b)
{
    const int idx = blockIdx.x * blockDim.x + threadIdx.x;
    const int stride = gridDim.x * blockDim.x;
    for (int i = idx; i < 256 * 512; i += stride) {
        int k = i >> 9, j = i & 511;
        g_encT[i] = (k < 128) ? enc_Wih[(size_t)j * 128 + k]
                              : enc_Whh[(size_t)j * 128 + (k - 128)];
    }
    for (int i = idx; i < 128 * 512; i += stride) {
        int k = i >> 9, j = i & 511;
        g_cpreT[i] = ctl_Wih[(size_t)j * 640 + 5 * k];
    }
    for (int i = idx; i < 640 * 640; i += stride) {
        int k = i / 640, j = i - k * 640;
        float v;
        if (j < 512) {
            v = (k < 512) ? ctl_Wih[(size_t)j * 640 + 5 * (k >> 2) + 1 + (k & 3)]
                          : ctl_Whh[(size_t)j * 128 + (k - 512)];
        } else {
            int o = j - 512;
            v = (k < 512) ? out_W[(size_t)o * 640 + 128 + k]
                          : out_W[(size_t)o * 640 + (k - 512)];
        }
        g_cboH[i] = __float2half_rn(v);
    }
    for (int i = idx; i < 128 * 920; i += stride) {
        int k = i / 920, j = i - k * 920;
        g_ifcH[i] = __float2half_rn((j < IFACEn) ? iface_W[(size_t)j * 128 + k] : 0.f);
    }
    if (idx < 512) {
        g_benc[idx] = enc_bih[idx] + enc_bhh[idx];
        g_bctl[idx] = ctl_bih[idx] + ctl_bhh[idx];
    }
    if (idx < 920) g_bifc[idx] = (idx < IFACEn) ? iface_b[idx] : 0.f;
    if (idx < 128) g_bout[idx] = out_b[idx];
    if (idx < 2 * Bn) g_prog[idx] = 0;   // reset pipeline flags EVERY launch
}

__device__ __forceinline__ float sigm(float x) { return 1.0f / (1.0f + expf(-x)); }
__device__ __forceinline__ float softplusf(float x) {
    return (x > 0.f) ? (x + log1pf(expf(-x))) : log1pf(expf(x));
}
__device__ __forceinline__ float wsum(float v) {
    v += __shfl_xor_sync(0xffffffffu, v, 16);
    v += __shfl_xor_sync(0xffffffffu, v, 8);
    v += __shfl_xor_sync(0xffffffffu, v, 4);
    v += __shfl_xor_sync(0xffffffffu, v, 2);
    v += __shfl_xor_sync(0xffffffffu, v, 1);
    return v;
}
__device__ __forceinline__ float wmax(float v) {
    v = fmaxf(v, __shfl_xor_sync(0xffffffffu, v, 16));
    v = fmaxf(v, __shfl_xor_sync(0xffffffffu, v, 8));
    v = fmaxf(v, __shfl_xor_sync(0xffffffffu, v, 4));
    v = fmaxf(v, __shfl_xor_sync(0xffffffffu, v, 2));
    v = fmaxf(v, __shfl_xor_sync(0xffffffffu, v, 1));
    return v;
}
__device__ __forceinline__ float dot4(float4 a, float4 b) {
    return a.x * b.x + a.y * b.y + a.z * b.z + a.w * b.w;
}
__device__ __forceinline__ void fma2(ull& acc, ull w, ull x) {
    asm("fma.rn.f32x2 %0, %1, %2, %0;" : "+l"(acc) : "l"(w), "l"(x));
}
__device__ __forceinline__ ull packf2(float x) {
    ull r; asm("mov.b64 %0, {%1, %1};" : "=l"(r) : "f"(x)); return r;
}
__device__ __forceinline__ float2 unpackf2(ull v) {
    float2 r; asm("mov.b64 {%0, %1}, %2;" : "=f"(r.x), "=f"(r.y) : "l"(v)); return r;
}
__device__ __forceinline__ float4 comb4(ull aL0, ull aH0, ull aL1, ull aH1) {
    float2 l0 = unpackf2(aL0), h0 = unpackf2(aH0), l1 = unpackf2(aL1), h1 = unpackf2(aH1);
    return make_float4(l0.x + l1.x, l0.y + l1.y, h0.x + h1.x, h0.y + h1.y);
}
__device__ __forceinline__ float4 h4tof4(uint2 w) {
    __half2 lo = *(__half2*)&w.x, hi = *(__half2*)&w.y;
    float2 l = __half22float2(lo), h = __half22float2(hi);
    return make_float4(l.x, l.y, h.x, h.y);
}
__device__ __forceinline__ void dsmem_store(void* local_ptr, uint32_t peer, float v) {
    uint32_t la = (uint32_t)__cvta_generic_to_shared(local_ptr);
    uint32_t rem;
    asm volatile("mapa.shared::cluster.u32 %0, %1, %2;" : "=r"(rem) : "r"(la), "r"(peer));
    asm volatile("st.shared::cluster.f32 [%0], %1;" :: "r"(rem), "f"(v) : "memory");
}
__device__ __forceinline__ int ld_acquire(const int* p) {
    int v; asm volatile("ld.acquire.gpu.global.s32 %0, [%1];" : "=r"(v) : "l"(p)); return v;
}
__device__ __forceinline__ void st_release(int* p, int v) {
    asm volatile("st.release.gpu.global.s32 [%0], %1;" :: "l"(p), "r"(v));
}
#define CLUSTER_SYNC() do { \
    asm volatile("barrier.cluster.arrive.aligned;" ::: "memory"); \
    asm volatile("barrier.cluster.wait.aligned;" ::: "memory"); } while (0)

// fp32 GEMV block (encoder only)
#define GEMV_BLK2(WP, RS, K)                                                   \
    {                                                                          \
        float4 xv = *(const float4*)&xsrc[(K)];                                \
        ulonglong2 w0 = (WP)[(size_t)((K) + 0) * (RS)];                        \
        ulonglong2 w1 = (WP)[(size_t)((K) + 1) * (RS)];                        \
        ulonglong2 w2 = (WP)[(size_t)((K) + 2) * (RS)];                        \
        ulonglong2 w3 = (WP)[(size_t)((K) + 3) * (RS)];                        \
        ull x0 = packf2(xv.x), x1 = packf2(xv.y), x2 = packf2(xv.z), x3 = packf2(xv.w); \
        fma2(aL0, w0.x, x0); fma2(aH0, w0.y, x0);                              \
        fma2(aL1, w1.x, x1); fma2(aH1, w1.y, x1);                              \
        fma2(aL0, w2.x, x2); fma2(aH0, w2.y, x2);                              \
        fma2(aL1, w3.x, x3); fma2(aH1, w3.y, x3);                              \
    }

// fp16-weight GEMV block: 4 k's, 4 LDG.64 + converts, fp32 accumulate (a0,a1 float4)
#define GEMV_BLKH(WP, RS, K)                                                   \
    {                                                                          \
        float4 xv = *(const float4*)&xsrc[(K)];                                \
        float4 w0 = h4tof4((WP)[(size_t)((K) + 0) * (RS)]);                    \
        float4 w1 = h4tof4((WP)[(size_t)((K) + 1) * (RS)]);                    \
        float4 w2 = h4tof4((WP)[(size_t)((K) + 2) * (RS)]);                    \
        float4 w3 = h4tof4((WP)[(size_t)((K) + 3) * (RS)]);                    \
        a0.x += xv.x * w0.x; a0.y += xv.x * w0.y; a0.z += xv.x * w0.z; a0.w += xv.x * w0.w; \
        a1.x += xv.y * w1.x; a1.y += xv.y * w1.y; a1.z += xv.y * w1.z; a1.w += xv.y * w1.w; \
        a0.x += xv.z * w2.x; a0.y += xv.z * w2.y; a0.z += xv.z * w2.z; a0.w += xv.z * w2.w; \
        a1.x += xv.w * w3.x; a1.y += xv.w * w3.y; a1.z += xv.w * w3.z; a1.w += xv.w * w3.w; \
    }

// ===================== SMEM layouts =====================
struct EncSmem {
    float gp[4096];
    float xs[256];
    float bufo[512];
    float pe[2][512];
    float h[128], c[128];
};

struct Smem {
    float mem[Nn][Wn];     // 64KB
    float lnk[Nn][Nn];     // 64KB
    float gp[10752];       // [0,4096) gate-rv | [4096,6144) out-rv | [8192,10240) gate-h | [10240,10752) out-h
    float xs[640];         // [rv(512, w*4+r) | h_ctl(128)]
    float bufo[920];
    float pc[640];
    float pi[920];
    float c_ctl[Wn];
    float rw[Rn * Nn];
    float rwn[Rn * Nn];
    float ww[Nn];
    float prec[2][Nn];
    float usage[Nn];
    float rk[Rn][Wn];
    float er[Wn];
    float wv[Wn];
    float rstr[Rn];
    float rknorm[Rn];
    float rm[Rn][3];
    float xmraw[12];
    float wc[Nn];
    float uu[Nn];
    float psu[Nn];
    float nrm[Nn];         // persists across steps
    float rc[Rn][Nn];
    float fwv[Rn][Nn];
    float bwv[Rn][Nn];
    float red[32];
    float scal[8];
    int   rnk[Nn];
};

// ===================== merged kernel: 64 DNC CTAs + 64 enc CTAs =====================
__global__ void __launch_bounds__(NTH, 1) __cluster_dims__(2, 1, 1) dnc_kernel(
    const float* __restrict__ input,
    float* __restrict__ out)
{
    extern __shared__ char smraw[];
    const int tid = threadIdx.x;
    const int wid = tid >> 5;
    const int lane = tid & 31;

    // ================= ENCODER ROLE (CTAs 64..127) =================
    if (blockIdx.x >= 2 * Bn) {
        EncSmem* s = reinterpret_cast<EncSmem*>(smraw);
        const int b = (blockIdx.x - 2 * Bn) >> 1;
        const uint32_t rank = blockIdx.x & 1;
        const uint32_t peer = rank ^ 1;

        if (tid < 128) { s->h[tid] = 0.f; s->c[tid] = 0.f; }
        __syncthreads();

        for (int t = 0; t < Tn; ++t) {
            if (tid < 128) {
                s->xs[tid] = input[((size_t)b * Tn + t) * Wn + tid];
                s->xs[128 + tid] = s->h[tid];
            }
            __syncthreads();
            {
                const int u = tid & 127, kc = tid >> 7;
                const ulonglong2* wp = ((const ulonglong2*)g_encT) + u;
                const float* xsrc = s->xs;
                ull aL0 = 0, aH0 = 0, aL1 = 0, aH1 = 0;
                const int k0 = (int)rank * 128 + kc * 16;
#pragma unroll
                for (int kk = 0; kk < 16; kk += 4) GEMV_BLK2(wp, 128, k0 + kk);
                ((float4*)s->gp)[kc * 128 + u] = comb4(aL0, aH0, aL1, aH1);
            }
            __syncthreads();
            if (tid < 512) {
                float p = 0.f;
#pragma unroll
                for (int kc = 0; kc < 8; ++kc) p += s->gp[kc * 512 + tid];
                s->bufo[tid] = p;
                dsmem_store(&s->pe[t & 1][tid], peer, p);
            }
            CLUSTER_SYNC();
            if (tid < 128) {
                const float* pe = s->pe[t & 1];
                float gi = sigm(s->bufo[tid]       + pe[tid]       + g_benc[tid]);
                float gf = sigm(s->bufo[128 + tid] + pe[128 + tid] + g_benc[128 + tid]);
                float gg = tanhf(s->bufo[256 + tid] + pe[256 + tid] + g_benc[256 + tid]);
                float go = sigm(s->bufo[384 + tid] + pe[384 + tid] + g_benc[384 + tid]);
                float c = gf * s->c[tid] + gi * gg;
                s->c[tid] = c;
                s->h[tid] = go * tanhf(c);
            }
            __syncthreads();
            {
                const int u = tid & 127, kc = tid >> 7;
                const ulonglong2* wp = ((const ulonglong2*)g_cpreT) + u;
                const float* xsrc = s->h;
                ull aL0 = 0, aH0 = 0, aL1 = 0, aH1 = 0;
                const int k0 = (int)rank * 64 + kc * 8;
#pragma unroll
                for (int kk = 0; kk < 8; kk += 4) GEMV_BLK2(wp, 128, k0 + kk);
                ((float4*)s->gp)[kc * 128 + u] = comb4(aL0, aH0, aL1, aH1);
            }
            __syncthreads();
            if (tid < 512) {
                float p = 0.f;
#pragma unroll
                for (int kc = 0; kc < 8; ++kc) p += s->gp[kc * 512 + tid];
                g_ctlpre[((size_t)b * Tn + t) * 1024 + rank * 512 + tid] = p;
                __threadfence();
            }
            __syncthreads();
            if (tid == 0) st_release(&g_prog[2 * b + rank], t + 1);
            __syncthreads();
        }
        return;
    }

    // ================= DNC ROLE (CTAs 0..63) =================
    Smem* s = reinterpret_cast<Smem*>(smraw);
    const int b = blockIdx.x >> 1;
    const uint32_t rank = blockIdx.x & 1;
    const uint32_t peer = rank ^ 1;
    const float* __restrict__ cpre_base = g_ctlpre + (size_t)b * Tn * 1024;

    // ---- zero recurrent state ----
    {
        float* p = &s->mem[0][0];
        for (int i = tid; i < Nn * Wn + Nn * Nn; i += NTH) p[i] = 0.f;
        if (tid < Wn) {
            s->c_ctl[tid] = 0.f; s->ww[tid] = 0.f;
            s->prec[0][tid] = 0.f; s->usage[tid] = 0.f; s->nrm[tid] = 0.f;
        }
        if (tid < 640) s->xs[tid] = 0.f;
        if (tid < 512) s->rw[tid] = 0.f;
        for (int i = tid; i < 2560; i += NTH) s->gp[8192 + i] = 0.f;  // h-partials (exact: h0=0)
    }
    __syncthreads();

    for (int t = 0; t <= Tn; ++t) {
        // ===== A: gates+out GEMV, rv-part only (h-part precomputed in F of t-1) =====
        {
            const int u = tid & 127, kc = tid >> 7;
            const uint2* wp = ((const uint2*)g_cboH) + u;
            const float* xsrc = s->xs;
            float4 a0 = make_float4(0, 0, 0, 0), a1 = a0;
            const int k0 = (int)rank * 256 + kc * 32;
#pragma unroll
            for (int kk = 0; kk < 32; kk += 4) GEMV_BLKH(wp, 160, k0 + kk);
            ((float4*)s->gp)[kc * 128 + u] =
                make_float4(a0.x + a1.x, a0.y + a1.y, a0.z + a1.z, a0.w + a1.w);
            if (tid < 512) {
                const int u2 = tid & 31, kc2 = tid >> 5;
                const uint2* wp2 = ((const uint2*)g_cboH) + 128 + u2;
                float4 b0 = make_float4(0, 0, 0, 0), b1 = b0;
                const int k0o = (int)rank * 256 + kc2 * 16;
#pragma unroll
                for (int kk = 0; kk < 16; kk += 2) {
                    float2 xv2 = *(const float2*)&xsrc[k0o + kk];
                    float4 w0 = h4tof4(wp2[(size_t)(k0o + kk) * 160]);
                    float4 w1 = h4tof4(wp2[(size_t)(k0o + kk + 1) * 160]);
                    b0.x += xv2.x * w0.x; b0.y += xv2.x * w0.y; b0.z += xv2.x * w0.z; b0.w += xv2.x * w0.w;
                    b1.x += xv2.y * w1.x; b1.y += xv2.y * w1.y; b1.z += xv2.y * w1.z; b1.w += xv2.y * w1.w;
                }
                ((float4*)s->gp)[1024 + kc2 * 32 + u2] =
                    make_float4(b0.x + b1.x, b0.y + b1.y, b0.z + b1.z, b0.w + b1.w);
            }
        }
        __syncthreads();
        // ===== reduce (rv + precomputed h partials) + exchange; warp 30 spins for encoder =====
        if (tid < 512) {
            float p = 0.f;
#pragma unroll
            for (int kc = 0; kc < 8; ++kc) p += s->gp[kc * 512 + tid];
#pragma unroll
            for (int c = 0; c < 4; ++c) p += s->gp[8192 + c * 512 + tid];
            s->bufo[tid] = p;
            dsmem_store(&s->pc[tid], peer, p);
        } else if (tid < 640) {
            const int o = tid - 512;
            float p = 0.f;
#pragma unroll
            for (int kc = 0; kc < 16; ++kc) p += s->gp[4096 + kc * 128 + o];
#pragma unroll
            for (int c = 0; c < 4; ++c) p += s->gp[10240 + c * 128 + o];
            s->bufo[tid] = p;
            dsmem_store(&s->pc[tid], peer, p);
        } else if (wid == 30 && lane == 0 && t < Tn) {
            while (ld_acquire(&g_prog[2 * b]) < t + 1 ||
                   ld_acquire(&g_prog[2 * b + 1]) < t + 1)
                __nanosleep(64);
        }
        CLUSTER_SYNC();
        // out row t-1
        if (t > 0 && rank == 0 && tid >= 512 && tid < 640)
            out[((size_t)b * Tn + (t - 1)) * Wn + (tid - 512)] =
                s->bufo[tid] + s->pc[tid] + g_bout[tid - 512];
        if (t == Tn) break;
        const int pcur = t & 1, pnxt = pcur ^ 1;
        // ctl cell
        if (tid < Wn) {
            const float* cp = cpre_base + (size_t)t * 1024;
            float gi = s->bufo[tid]       + s->pc[tid]       + __ldcg(cp + tid)       + __ldcg(cp + 512 + tid) + g_bctl[tid];
            float gf = s->bufo[128 + tid] + s->pc[128 + tid] + __ldcg(cp + 128 + tid) + __ldcg(cp + 640 + tid) + g_bctl[128 + tid];
            float gg = s->bufo[256 + tid] + s->pc[256 + tid] + __ldcg(cp + 256 + tid) + __ldcg(cp + 768 + tid) + g_bctl[256 + tid];
            float go = s->bufo[384 + tid] + s->pc[384 + tid] + __ldcg(cp + 384 + tid) + __ldcg(cp + 896 + tid) + g_bctl[384 + tid];
            gi = sigm(gi); gf = sigm(gf); gg = tanhf(gg); go = sigm(go);
            float c = gf * s->c_ctl[tid] + gi * gg;
            s->c_ctl[tid] = c;
            s->xs[512 + tid] = go * tanhf(c);
        }
        __syncthreads();

        // ===== iface GEMV (fp16 weights) =====
        if (tid < 920) {
            const int kc = tid / 230, u = tid - kc * 230;
            const uint2* wp = ((const uint2*)g_ifcH) + u;
            const float* xsrc = s->xs + 512;
            float4 a0 = make_float4(0, 0, 0, 0), a1 = a0;
            const int k0 = (int)rank * 64 + kc * 16;
#pragma unroll
            for (int kk = 0; kk < 16; kk += 4) GEMV_BLKH(wp, 230, k0 + kk);
            ((float4*)(s->gp + kc * 920))[u] =
                make_float4(a0.x + a1.x, a0.y + a1.y, a0.z + a1.z, a0.w + a1.w);
        }
        __syncthreads();
        if (tid < 920) {
            float p = s->gp[tid] + s->gp[920 + tid] + s->gp[1840 + tid] + s->gp[2760 + tid];
            s->bufo[tid] = p;
            dsmem_store(&s->pi[tid], peer, p);
        }
        CLUSTER_SYNC();

        // ===== D+E fused: {usage+uu (w0-3)} || {parse (w4-11)} || {mem.wk dots, wk inline (w16-31)} =====
        if (wid < 4) {
            float fgv = 0.f;
            if (lane < 4) fgv = sigm(s->bufo[901 + lane] + s->pi[901 + lane] + g_bifc[901 + lane]);
            float fg0 = __shfl_sync(0xffffffffu, fgv, 0);
            float fg1 = __shfl_sync(0xffffffffu, fgv, 1);
            float fg2 = __shfl_sync(0xffffffffu, fgv, 2);
            float fg3 = __shfl_sync(0xffffffffu, fgv, 3);
            float us = s->usage[tid];
            us = us + (1.f - us) * s->ww[tid];
            float ret = (1.f - fg0 * s->rw[tid])
                      * (1.f - fg1 * s->rw[Nn + tid])
                      * (1.f - fg2 * s->rw[2 * Nn + tid])
                      * (1.f - fg3 * s->rw[3 * Nn + tid]);
            us *= ret;
            s->usage[tid] = us;
            s->uu[tid] = DELTAf + (1.f - DELTAf) * us;
        } else if (wid < 12) {
            const int base = tid - 128;
#pragma unroll
            for (int q = 0; q < 4; ++q) {
                int j = base + 256 * q;
                if (j >= IFACEn) break;
                float v = s->bufo[j] + s->pi[j] + g_bifc[j];
                if (j < 512)       ((float*)s->rk)[j] = tanhf(v);
                else if (j < 516)  s->rstr[j - 512] = softplusf(v);
                else if (j == 644) s->scal[0] = softplusf(v);
                else if (j >= 645 && j < 773) s->er[j - 645] = sigm(v);
                else if (j >= 773 && j < 901) s->wv[j - 773] = tanhf(v);
                else if (j == 905) s->scal[1] = sigm(v);
                else if (j == 906) s->scal[2] = sigm(v);
                else if (j >= 907) s->xmraw[j - 907] = v;
            }
        } else if (wid >= 16) {
            const int o = 516 + lane * 4;
            float4 bf = *(const float4*)&s->bufo[o];
            float4 pf = *(const float4*)&s->pi[o];
            float4 gf4 = *(const float4*)&g_bifc[o];
            float4 k4 = make_float4(tanhf(bf.x + pf.x + gf4.x), tanhf(bf.y + pf.y + gf4.y),
                                    tanhf(bf.z + pf.z + gf4.z), tanhf(bf.w + pf.w + gf4.w));
            if (wid == 16) {
                float nv = wsum(dot4(k4, k4));
                if (lane == 0) s->scal[3] = sqrtf(nv);
            }
            const int n0 = (wid - 16) * 8;
#pragma unroll
            for (int rr = 0; rr < 8; ++rr) {
                int n = n0 + rr;
                float4 m4 = ((const float4*)s->mem[n])[lane];
                float dk = wsum(dot4(m4, k4));
                if (lane == 0) s->wc[n] = dk;
            }
        }
        __syncthreads();

        // ===== F: {rank+scan+alloc+ww (w0-3)} || {wc softmax (w8)} || {rm (w5)} || {rknorm (w12-15)}
        //        || {next-A gate-h prefetch (w16-31)} || {next-A out-h prefetch (w4,6,7,9)} =====
        if (tid < Nn) {
            float un = s->uu[tid];
            const float4* uu4 = (const float4*)s->uu;
            int rk_ = 0;
#pragma unroll 8
            for (int j4 = 0; j4 < 32; ++j4) {
                float4 u4 = uu4[j4];
                int j = j4 * 4;
                rk_ += (u4.x < un) || (u4.x == un && j + 0 < tid);
                rk_ += (u4.y < un) || (u4.y == un && j + 1 < tid);
                rk_ += (u4.z < un) || (u4.z == un && j + 2 < tid);
                rk_ += (u4.w < un) || (u4.w == un && j + 3 < tid);
            }
            s->rnk[tid] = rk_;
            s->psu[rk_] = un;
            asm volatile("bar.sync 1, 128;" ::: "memory");
            if (wid == 0) {
                float v0 = s->psu[lane * 4], v1 = s->psu[lane * 4 + 1];
                float v2 = s->psu[lane * 4 + 2], v3 = s->psu[lane * 4 + 3];
                float l1 = v0 * v1, l2 = l1 * v2, l3 = l2 * v3;
                float run = l3;
#pragma unroll
                for (int off = 1; off < 32; off <<= 1) {
                    float up = __shfl_up_sync(0xffffffffu, run, off);
                    if (lane >= off) run *= up;
                }
                float ex = __shfl_up_sync(0xffffffffu, run, 1);
                if (lane == 0) ex = 1.f;
                s->psu[lane * 4]     = ex * v0;
                s->psu[lane * 4 + 1] = ex * l1;
                s->psu[lane * 4 + 2] = ex * l2;
                s->psu[lane * 4 + 3] = ex * l3;
            }
            asm volatile("bar.sync 1, 128;" ::: "memory");
            asm volatile("bar.sync 2, 160;" ::: "memory");
            {
                int r_ = s->rnk[tid];
                float excl = (r_ == 0) ? 1.f : s->psu[r_ - 1];
                float alloc = (1.f - s->uu[tid]) * excl;
                float ag = s->scal[1], wg = s->scal[2];
                float v = wg * (ag * alloc + (1.f - ag) * s->wc[tid]);
                s->ww[tid] = v;
                float sm = wsum(v);
                if (lane == 0) s->red[wid] = sm;
            }
        } else if (wid == 8) {
            float inw = 1.f / ((s->scal[3] + DELTAf));
            float ws = s->scal[0];
            float v[4];
            float mx = -1e30f;
#pragma unroll
            for (int q = 0; q < 4; ++q) {
                int n = lane + 32 * q;
                v[q] = s->wc[n] / (s->nrm[n] + DELTAf) * inw * ws;
                mx = fmaxf(mx, v[q]);
            }
            mx = wmax(mx);
            float sm = 0.f;
#pragma unroll
            for (int q = 0; q < 4; ++q) { v[q] = expf(v[q] - mx); sm += v[q]; }
            sm = wsum(sm);
            float inv = 1.f / sm;
#pragma unroll
            for (int q = 0; q < 4; ++q) s->wc[lane + 32 * q] = v[q] * inv;
            asm volatile("bar.sync 2, 160;" ::: "memory");
        } else if (wid == 5 && lane < Rn) {
            int r = lane;
            float a = s->xmraw[r * 3], b2 = s->xmraw[r * 3 + 1], c2 = s->xmraw[r * 3 + 2];
            float m = fmaxf(a, fmaxf(b2, c2));
            float ea = expf(a - m), eb = expf(b2 - m), ec = expf(c2 - m);
            float inv = 1.f / (ea + eb + ec);
            s->rm[r][0] = ea * inv; s->rm[r][1] = eb * inv; s->rm[r][2] = ec * inv;
        } else if (wid >= 12 && wid < 12 + Rn) {
            int r = wid - 12;
            float4 k4 = ((const float4*)s->rk[r])[lane];
            float nv = wsum(dot4(k4, k4));
            if (lane == 0) s->rknorm[r] = sqrtf(nv);
        } else if (wid >= 16) {
            // gate-h prefetch for A(t+1): fp16 weights
            const int idx = tid - 512;
            const int u = idx & 127, c = idx >> 7;
            const uint2* wp = ((const uint2*)g_cboH) + u;
            const float* xsrc = s->xs;
            float4 a0 = make_float4(0, 0, 0, 0), a1 = a0;
            const int k0h = 512 + (int)rank * 64 + c * 16;
#pragma unroll
            for (int kk = 0; kk < 16; kk += 4) GEMV_BLKH(wp, 160, k0h + kk);
            ((float4*)s->gp)[2048 + c * 128 + u] =
                make_float4(a0.x + a1.x, a0.y + a1.y, a0.z + a1.z, a0.w + a1.w);
        } else if (wid == 4 || wid == 6 || wid == 7 || wid == 9) {
            // out-h prefetch: fp16 weights
            const int wmap = (wid == 4) ? 0 : (wid == 6) ? 1 : (wid == 7) ? 2 : 3;
            const int idx2 = wmap * 32 + lane;
            const int u2 = idx2 & 31, c2 = idx2 >> 5;
            const uint2* wp2 = ((const uint2*)g_cboH) + 128 + u2;
            const float* xsrc = s->xs;
            float4 b0 = make_float4(0, 0, 0, 0), b1 = b0;
            const int k0h = 512 + (int)rank * 64 + c2 * 16;
#pragma unroll
            for (int kk = 0; kk < 16; kk += 2) {
                float2 xv2 = *(const float2*)&xsrc[k0h + kk];
                float4 w0 = h4tof4(wp2[(size_t)(k0h + kk) * 160]);
                float4 w1 = h4tof4(wp2[(size_t)(k0h + kk + 1) * 160]);
                b0.x += xv2.x * w0.x; b0.y += xv2.x * w0.y; b0.z += xv2.x * w0.z; b0.w += xv2.x * w0.w;
                b1.x += xv2.y * w1.x; b1.y += xv2.y * w1.y; b1.z += xv2.y * w1.z; b1.w += xv2.y * w1.w;
            }
            ((float4*)s->gp)[2560 + c2 * 32 + u2] =
                make_float4(b0.x + b1.x, b0.y + b1.y, b0.z + b1.z, b0.w + b1.w);
        }
        __syncthreads();

        // ===== G: mem erase+write fused with new-mem dots; link update; prec =====
        {
            float4 k0 = ((const float4*)s->rk[0])[lane];
            float4 k1 = ((const float4*)s->rk[1])[lane];
            float4 k2 = ((const float4*)s->rk[2])[lane];
            float4 k3 = ((const float4*)s->rk[3])[lane];
            float4* m4 = (float4*)s->mem;
            float4 e = ((const float4*)s->er)[lane], v = ((const float4*)s->wv)[lane];
#pragma unroll
            for (int it = 0; it < 4; ++it) {
                int idx = tid + it * NTH;
                int n = wid + it * 32;
                float wwn = s->ww[n];
                float4 m = m4[idx];
                m.x = m.x * (1.f - wwn * e.x) + wwn * v.x;
                m.y = m.y * (1.f - wwn * e.y) + wwn * v.y;
                m.z = m.z * (1.f - wwn * e.z) + wwn * v.z;
                m.w = m.w * (1.f - wwn * e.w) + wwn * v.w;
                m4[idx] = m;
                float dn = wsum(dot4(m, m));
                float d0 = wsum(dot4(m, k0));
                float d1 = wsum(dot4(m, k1));
                float d2 = wsum(dot4(m, k2));
                float d3 = wsum(dot4(m, k3));
                if (lane == 0) {
                    s->nrm[n] = sqrtf(dn);
                    s->rc[0][n] = d0; s->rc[1][n] = d1; s->rc[2][n] = d2; s->rc[3][n] = d3;
                }
            }
            float4* l4 = (float4*)s->lnk;
            const float4* wwp = (const float4*)s->ww;
            const float4* pcp = (const float4*)s->prec[pcur];
#pragma unroll
            for (int it = 0; it < 4; ++it) {
                int idx = tid + it * NTH;
                int i = idx >> 5, q = idx & 31;
                float wwi = s->ww[i];
                float4 L = l4[idx], wj = wwp[q], pj = pcp[q];
                L.x = (1.f - wwi - wj.x) * L.x + wwi * pj.x;
                L.y = (1.f - wwi - wj.y) * L.y + wwi * pj.y;
                L.z = (1.f - wwi - wj.z) * L.z + wwi * pj.z;
                L.w = (1.f - wwi - wj.w) * L.w + wwi * pj.w;
                if ((i >> 2) == q) ((float*)&L)[i & 3] = 0.f;
                l4[idx] = L;
            }
            if (wid == 31) {
                float vv = (lane < 4) ? s->red[lane] : 0.f;
                float sw = wsum(vv);
#pragma unroll
                for (int q = 0; q < 4; ++q) {
                    int n = lane + 32 * q;
                    s->prec[pnxt][n] = (1.f - sw) * s->prec[pcur][n] + s->ww[n];
                }
            }
        }
        __syncthreads();

        // ===== H: {read softmax (w0-3)} || {bw col-acc all-r (w4-7)} || {fw row-dots (w8-31)} =====
        if (wid < Rn) {
            int r_ = wid;
            float inv_kn = 1.f / (s->rknorm[r_] + DELTAf);
            float rs = s->rstr[r_];
            float v[4];
            float mx = -1e30f;
#pragma unroll
            for (int q = 0; q < 4; ++q) {
                int n = lane + 32 * q;
                v[q] = s->rc[r_][n] / (s->nrm[n] + DELTAf) * inv_kn * rs;
                mx = fmaxf(mx, v[q]);
            }
            mx = wmax(mx);
            float sm = 0.f;
#pragma unroll
            for (int q = 0; q < 4; ++q) { v[q] = expf(v[q] - mx); sm += v[q]; }
            sm = wsum(sm);
            float inv = 1.f / sm;
#pragma unroll
            for (int q = 0; q < 4; ++q) s->rc[r_][lane + 32 * q] = v[q] * inv;
        } else if (wid < 8) {
            const int i = (wid - 4) * 32 + lane;
            const float4* rwA = (const float4*)(s->rw);
            const float4* rwB = (const float4*)(s->rw + Nn);
            const float4* rwC = (const float4*)(s->rw + 2 * Nn);
            const float4* rwD = (const float4*)(s->rw + 3 * Nn);
            float a0 = 0.f, a1 = 0.f, a2 = 0.f, a3 = 0.f;
#pragma unroll 4
            for (int j4 = 0; j4 < 32; ++j4) {
                float4 wA = rwA[j4], wB = rwB[j4], wC = rwC[j4], wD = rwD[j4];
                int j = j4 * 4;
                float L0 = s->lnk[j][i], L1 = s->lnk[j + 1][i];
                float L2 = s->lnk[j + 2][i], L3 = s->lnk[j + 3][i];
                a0 += wA.x * L0 + wA.y * L1 + wA.z * L2 + wA.w * L3;
                a1 += wB.x * L0 + wB.y * L1 + wB.z * L2 + wB.w * L3;
                a2 += wC.x * L0 + wC.y * L1 + wC.z * L2 + wC.w * L3;
                a3 += wD.x * L0 + wD.y * L1 + wD.z * L2 + wD.w * L3;
            }
            s->bwv[0][i] = a0; s->bwv[1][i] = a1; s->bwv[2][i] = a2; s->bwv[3][i] = a3;
        } else {
            float4 w0 = ((const float4*)s->rw)[lane];
            float4 w1 = ((const float4*)s->rw)[32 + lane];
            float4 w2 = ((const float4*)s->rw)[64 + lane];
            float4 w3 = ((const float4*)s->rw)[96 + lane];
            for (int i = wid - 8; i < Nn; i += 24) {
                float4 L = ((const float4*)s->lnk[i])[lane];
                float d0 = wsum(dot4(L, w0));
                float d1 = wsum(dot4(L, w1));
                float d2 = wsum(dot4(L, w2));
                float d3 = wsum(dot4(L, w3));
                if (lane == 0) {
                    s->fwv[0][i] = d0; s->fwv[1][i] = d1;
                    s->fwv[2][i] = d2; s->fwv[3][i] = d3;
                }
            }
        }
        __syncthreads();

        // ===== I (merged): {rwn combine + rw commit (w4-19)} -> named bar 640 -> {rv (w0-3)} =====
        if (wid < 20) {
            if (wid >= 4) {
                const int idx = tid - 128;   // 0..511
                const int r_ = idx >> 7, i = idx & 127;
                float val = s->rm[r_][0] * s->bwv[r_][i]
                          + s->rm[r_][1] * s->fwv[r_][i]
                          + s->rm[r_][2] * s->rc[r_][i];
                s->rwn[idx] = val;
                s->rw[idx] = val;
            }
            asm volatile("bar.sync 3, 640;" ::: "memory");
            if (wid < 4) {
                const int wcol = wid * 32 + lane;
                const float4* rnA = (const float4*)(s->rwn);
                const float4* rnB = (const float4*)(s->rwn + Nn);
                const float4* rnC = (const float4*)(s->rwn + 2 * Nn);
                const float4* rnD = (const float4*)(s->rwn + 3 * Nn);
                float a0 = 0.f, a1 = 0.f, a2 = 0.f, a3 = 0.f;
#pragma unroll 4
                for (int n4 = 0; n4 < 32; ++n4) {
                    float4 wA = rnA[n4], wB = rnB[n4], wC = rnC[n4], wD = rnD[n4];
                    int n = n4 * 4;
                    float M0 = s->mem[n][wcol], M1 = s->mem[n + 1][wcol];
                    float M2 = s->mem[n + 2][wcol], M3 = s->mem[n + 3][wcol];
                    a0 += wA.x * M0 + wA.y * M1 + wA.z * M2 + wA.w * M3;
                    a1 += wB.x * M0 + wB.y * M1 + wB.z * M2 + wB.w * M3;
                    a2 += wC.x * M0 + wC.y * M1 + wC.z * M2 + wC.w * M3;
                    a3 += wD.x * M0 + wD.y * M1 + wD.z * M2 + wD.w * M3;
                }
                ((float4*)s->xs)[wcol] = make_float4(a0, a1, a2, a3);
            }
        }
        __syncthreads();
    }
}

extern "C" void kernel_launch(void* const* d_in, const int* in_sizes, int n_in,
                              void* d_out, int out_size) {
    const float* input   = (const float*)d_in[0];
    // d_in[1] = source_lengths (all == T, unused)
    const float* enc_Wih = (const float*)d_in[2];
    const float* enc_Whh = (const float*)d_in[3];
    const float* enc_bih = (const float*)d_in[4];
    const float* enc_bhh = (const float*)d_in[5];
    const float* ctl_Wih = (const float*)d_in[6];
    const float* ctl_Whh = (const float*)d_in[7];
    const float* ctl_bih = (const float*)d_in[8];
    const float* ctl_bhh = (const float*)d_in[9];
    const float* iface_W = (const float*)d_in[10];
    const float* iface_b = (const float*)d_in[11];
    const float* out_W   = (const float*)d_in[12];
    const float* out_b   = (const float*)d_in[13];
    float* out = (float*)d_out;

    prep_kernel<<<448, 256>>>(enc_Wih, enc_Whh, enc_bih, enc_bhh,
                              ctl_Wih, ctl_Whh, ctl_bih, ctl_bhh,
                              iface_W, iface_b, out_W, out_b);

    int smem = (int)sizeof(Smem);
    cudaFuncSetAttribute(dnc_kernel, cudaFuncAttributeMaxDynamicSharedMemorySize, smem);
    // 64 DNC + 64 encoder CTAs = 128 <= 148 SMs, occupancy 1/SM, all wave-1 resident;
    // producer/consumer spin (g_prog, reset by prep each launch) is deadlock-free.
    dnc_kernel<<<4 * Bn, NTH, smem>>>(input, out);
}

// round 16
// speedup vs baseline: 1.0208x; 1.0208x over previous
#include <cuda_runtime.h>
#include <cuda_fp16.h>
#include <cstddef>
#include <cstdint>

#define Bn 32
#define Tn 256
#define Wn 128
#define Rn 4
#define Nn 128
#define IFACEn 919
#define NTH 1024
#define DELTAf 1e-6f

typedef unsigned long long ull;

// -------- transposed-weight scratch + pipeline buffers (device globals) --------
__device__ float  g_encT[256 * 512];    // [k][j] fp32 (encoder, latency-hidden)
__device__ float  g_cpreT[128 * 512];   // [k][j] fp32
__device__ __half g_cboH[640 * 640];    // [k][j] fp16: k = rv(512)||h(128); j = gates(512)||out(128)
__device__ __half g_ifcH[128 * 920];    // [k][j] fp16, j padded 919->920
__device__ float  g_benc[512];
__device__ float  g_bctl[512];
__device__ float  g_bifc[920];
__device__ float  g_bout[128];
__device__ float  g_ctlpre[(size_t)Bn * Tn * 1024];
__device__ int    g_prog[2 * Bn];

__global__ void prep_kernel(
    const float* __restrict__ enc_Wih, const float* __restrict__ enc_Whh,
    const float* __restrict__ enc_bih, const float* __restrict__ enc_bhh,
    const float* __restrict__ ctl_Wih, const float* __restrict__ ctl_Whh,
    const float* __restrict__ ctl_bih, const float* __restrict__ ctl_bhh,
    const float* __restrict__ iface_W, const float* __restrict__ iface_b,
    const float* __restrict__ out_W, const float* __restrict__ out_b)
{
    const int idx = blockIdx.x * blockDim.x + threadIdx.x;
    const int stride = gridDim.x * blockDim.x;
    for (int i = idx; i < 256 * 512; i += stride) {
        int k = i >> 9, j = i & 511;
        g_encT[i] = (k < 128) ? enc_Wih[(size_t)j * 128 + k]
                              : enc_Whh[(size_t)j * 128 + (k - 128)];
    }
    for (int i = idx; i < 128 * 512; i += stride) {
        int k = i >> 9, j = i & 511;
        g_cpreT[i] = ctl_Wih[(size_t)j * 640 + 5 * k];
    }
    for (int i = idx; i < 640 * 640; i += stride) {
        int k = i / 640, j = i - k * 640;
        float v;
        if (j < 512) {
            v = (k < 512) ? ctl_Wih[(size_t)j * 640 + 5 * (k >> 2) + 1 + (k & 3)]
                          : ctl_Whh[(size_t)j * 128 + (k - 512)];
        } else {
            int o = j - 512;
            v = (k < 512) ? out_W[(size_t)o * 640 + 128 + k]
                          : out_W[(size_t)o * 640 + (k - 512)];
        }
        g_cboH[i] = __float2half_rn(v);
    }
    for (int i = idx; i < 128 * 920; i += stride) {
        int k = i / 920, j = i - k * 920;
        g_ifcH[i] = __float2half_rn((j < IFACEn) ? iface_W[(size_t)j * 128 + k] : 0.f);
    }
    if (idx < 512) {
        g_benc[idx] = enc_bih[idx] + enc_bhh[idx];
        g_bctl[idx] = ctl_bih[idx] + ctl_bhh[idx];
    }
    if (idx < 920) g_bifc[idx] = (idx < IFACEn) ? iface_b[idx] : 0.f;
    if (idx < 128) g_bout[idx] = out_b[idx];
    if (idx < 2 * Bn) g_prog[idx] = 0;   // reset pipeline flags EVERY launch
}

__device__ __forceinline__ float sigm(float x) { return 1.0f / (1.0f + expf(-x)); }
__device__ __forceinline__ float softplusf(float x) {
    return (x > 0.f) ? (x + log1pf(expf(-x))) : log1pf(expf(x));
}
__device__ __forceinline__ float wsum(float v) {
    v += __shfl_xor_sync(0xffffffffu, v, 16);
    v += __shfl_xor_sync(0xffffffffu, v, 8);
    v += __shfl_xor_sync(0xffffffffu, v, 4);
    v += __shfl_xor_sync(0xffffffffu, v, 2);
    v += __shfl_xor_sync(0xffffffffu, v, 1);
    return v;
}
__device__ __forceinline__ float wmax(float v) {
    v = fmaxf(v, __shfl_xor_sync(0xffffffffu, v, 16));
    v = fmaxf(v, __shfl_xor_sync(0xffffffffu, v, 8));
    v = fmaxf(v, __shfl_xor_sync(0xffffffffu, v, 4));
    v = fmaxf(v, __shfl_xor_sync(0xffffffffu, v, 2));
    v = fmaxf(v, __shfl_xor_sync(0xffffffffu, v, 1));
    return v;
}
__device__ __forceinline__ float dot4(float4 a, float4 b) {
    return a.x * b.x + a.y * b.y + a.z * b.z + a.w * b.w;
}
__device__ __forceinline__ void fma2(ull& acc, ull w, ull x) {
    asm("fma.rn.f32x2 %0, %1, %2, %0;" : "+l"(acc) : "l"(w), "l"(x));
}
__device__ __forceinline__ ull packf2(float x) {
    ull r; asm("mov.b64 %0, {%1, %1};" : "=l"(r) : "f"(x)); return r;
}
__device__ __forceinline__ float2 unpackf2(ull v) {
    float2 r; asm("mov.b64 {%0, %1}, %2;" : "=f"(r.x), "=f"(r.y) : "l"(v)); return r;
}
__device__ __forceinline__ float4 comb4(ull aL0, ull aH0, ull aL1, ull aH1) {
    float2 l0 = unpackf2(aL0), h0 = unpackf2(aH0), l1 = unpackf2(aL1), h1 = unpackf2(aH1);
    return make_float4(l0.x + l1.x, l0.y + l1.y, h0.x + h1.x, h0.y + h1.y);
}
__device__ __forceinline__ float4 h4tof4(uint2 w) {
    __half2 lo = *(__half2*)&w.x, hi = *(__half2*)&w.y;
    float2 l = __half22float2(lo), h = __half22float2(hi);
    return make_float4(l.x, l.y, h.x, h.y);
}
__device__ __forceinline__ void dsmem_store(void* local_ptr, uint32_t peer, float v) {
    uint32_t la = (uint32_t)__cvta_generic_to_shared(local_ptr);
    uint32_t rem;
    asm volatile("mapa.shared::cluster.u32 %0, %1, %2;" : "=r"(rem) : "r"(la), "r"(peer));
    asm volatile("st.shared::cluster.f32 [%0], %1;" :: "r"(rem), "f"(v) : "memory");
}
__device__ __forceinline__ int ld_acquire(const int* p) {
    int v; asm volatile("ld.acquire.gpu.global.s32 %0, [%1];" : "=r"(v) : "l"(p)); return v;
}
__device__ __forceinline__ void st_release(int* p, int v) {
    asm volatile("st.release.gpu.global.s32 [%0], %1;" :: "l"(p), "r"(v));
}
#define CLUSTER_SYNC() do { \
    asm volatile("barrier.cluster.arrive.aligned;" ::: "memory"); \
    asm volatile("barrier.cluster.wait.aligned;" ::: "memory"); } while (0)

// fp32 GEMV block (encoder only)
#define GEMV_BLK2(WP, RS, K)                                                   \
    {                                                                          \
        float4 xv = *(const float4*)&xsrc[(K)];                                \
        ulonglong2 w0 = (WP)[(size_t)((K) + 0) * (RS)];                        \
        ulonglong2 w1 = (WP)[(size_t)((K) + 1) * (RS)];                        \
        ulonglong2 w2 = (WP)[(size_t)((K) + 2) * (RS)];                        \
        ulonglong2 w3 = (WP)[(size_t)((K) + 3) * (RS)];                        \
        ull x0 = packf2(xv.x), x1 = packf2(xv.y), x2 = packf2(xv.z), x3 = packf2(xv.w); \
        fma2(aL0, w0.x, x0); fma2(aH0, w0.y, x0);                              \
        fma2(aL1, w1.x, x1); fma2(aH1, w1.y, x1);                              \
        fma2(aL0, w2.x, x2); fma2(aH0, w2.y, x2);                              \
        fma2(aL1, w3.x, x3); fma2(aH1, w3.y, x3);                              \
    }

// fp16-weight GEMV block: 4 k's, 4 LDG.64 + converts, fp32 accumulate (a0,a1 float4)
#define GEMV_BLKH(WP, RS, K)                                                   \
    {                                                                          \
        float4 xv = *(const float4*)&xsrc[(K)];                                \
        float4 w0 = h4tof4((WP)[(size_t)((K) + 0) * (RS)]);                    \
        float4 w1 = h4tof4((WP)[(size_t)((K) + 1) * (RS)]);                    \
        float4 w2 = h4tof4((WP)[(size_t)((K) + 2) * (RS)]);                    \
        float4 w3 = h4tof4((WP)[(size_t)((K) + 3) * (RS)]);                    \
        a0.x += xv.x * w0.x; a0.y += xv.x * w0.y; a0.z += xv.x * w0.z; a0.w += xv.x * w0.w; \
        a1.x += xv.y * w1.x; a1.y += xv.y * w1.y; a1.z += xv.y * w1.z; a1.w += xv.y * w1.w; \
        a0.x += xv.z * w2.x; a0.y += xv.z * w2.y; a0.z += xv.z * w2.z; a0.w += xv.z * w2.w; \
        a1.x += xv.w * w3.x; a1.y += xv.w * w3.y; a1.z += xv.w * w3.z; a1.w += xv.w * w3.w; \
    }

// ===================== SMEM layouts =====================
struct EncSmem {
    float gp[4096];
    float xs[256];
    float bufo[512];
    float pe[2][512];
    float h[128], c[128];
};

struct Smem {
    float mem[Nn][Wn];     // 64KB
    float lnk[Nn][Nn];     // 64KB
    float gp[8704];        // [0,4096) gate-rv | [4096,6144) out-rv | [6144,8192) gate-h | [8192,8704) out-h
    float xs[640];         // [rv(512, w*4+r) | h_ctl(128)]
    float bufo[920];
    float pc[640];
    float pi[920];
    float c_ctl[Wn];
    float rw[Rn * Nn];
    float rwn[Rn * Nn];
    float ww[Nn];
    float prec[2][Nn];
    float usage[Nn];
    float rk[Rn][Wn];
    float er[Wn];
    float wv[Wn];
    float rstr[Rn];
    float rknorm[Rn];
    float rm[Rn][3];
    float xmraw[12];
    float wc[Nn];
    float uu[Nn];
    float psu[Nn];
    float nrm[Nn];         // persists across steps
    float rc[Rn][Nn];
    float fwv[Rn][Nn];
    float bwv[Rn][Nn];
    float red[32];
    float scal[8];
    int   rnk[Nn];
};

// ===================== merged kernel: 64 DNC CTAs + 64 enc CTAs =====================
__global__ void __launch_bounds__(NTH, 1) __cluster_dims__(2, 1, 1) dnc_kernel(
    const float* __restrict__ input,
    float* __restrict__ out)
{
    extern __shared__ char smraw[];
    const int tid = threadIdx.x;
    const int wid = tid >> 5;
    const int lane = tid & 31;

    // ================= ENCODER ROLE (CTAs 64..127) =================
    if (blockIdx.x >= 2 * Bn) {
        EncSmem* s = reinterpret_cast<EncSmem*>(smraw);
        const int b = (blockIdx.x - 2 * Bn) >> 1;
        const uint32_t rank = blockIdx.x & 1;
        const uint32_t peer = rank ^ 1;

        if (tid < 128) { s->h[tid] = 0.f; s->c[tid] = 0.f; }
        __syncthreads();

        for (int t = 0; t < Tn; ++t) {
            if (tid < 128) {
                s->xs[tid] = input[((size_t)b * Tn + t) * Wn + tid];
                s->xs[128 + tid] = s->h[tid];
            }
            __syncthreads();
            {
                const int u = tid & 127, kc = tid >> 7;
                const ulonglong2* wp = ((const ulonglong2*)g_encT) + u;
                const float* xsrc = s->xs;
                ull aL0 = 0, aH0 = 0, aL1 = 0, aH1 = 0;
                const int k0 = (int)rank * 128 + kc * 16;
#pragma unroll
                for (int kk = 0; kk < 16; kk += 4) GEMV_BLK2(wp, 128, k0 + kk);
                ((float4*)s->gp)[kc * 128 + u] = comb4(aL0, aH0, aL1, aH1);
            }
            __syncthreads();
            if (tid < 512) {
                float p = 0.f;
#pragma unroll
                for (int kc = 0; kc < 8; ++kc) p += s->gp[kc * 512 + tid];
                s->bufo[tid] = p;
                dsmem_store(&s->pe[t & 1][tid], peer, p);
            }
            CLUSTER_SYNC();
            if (tid < 128) {
                const float* pe = s->pe[t & 1];
                float gi = sigm(s->bufo[tid]       + pe[tid]       + g_benc[tid]);
                float gf = sigm(s->bufo[128 + tid] + pe[128 + tid] + g_benc[128 + tid]);
                float gg = tanhf(s->bufo[256 + tid] + pe[256 + tid] + g_benc[256 + tid]);
                float go = sigm(s->bufo[384 + tid] + pe[384 + tid] + g_benc[384 + tid]);
                float c = gf * s->c[tid] + gi * gg;
                s->c[tid] = c;
                s->h[tid] = go * tanhf(c);
            }
            __syncthreads();
            {
                const int u = tid & 127, kc = tid >> 7;
                const ulonglong2* wp = ((const ulonglong2*)g_cpreT) + u;
                const float* xsrc = s->h;
                ull aL0 = 0, aH0 = 0, aL1 = 0, aH1 = 0;
                const int k0 = (int)rank * 64 + kc * 8;
#pragma unroll
                for (int kk = 0; kk < 8; kk += 4) GEMV_BLK2(wp, 128, k0 + kk);
                ((float4*)s->gp)[kc * 128 + u] = comb4(aL0, aH0, aL1, aH1);
            }
            __syncthreads();
            if (tid < 512) {
                float p = 0.f;
#pragma unroll
                for (int kc = 0; kc < 8; ++kc) p += s->gp[kc * 512 + tid];
                g_ctlpre[((size_t)b * Tn + t) * 1024 + rank * 512 + tid] = p;
                __threadfence();
            }
            __syncthreads();
            if (tid == 0) st_release(&g_prog[2 * b + rank], t + 1);
            __syncthreads();
        }
        return;
    }

    // ================= DNC ROLE (CTAs 0..63) =================
    Smem* s = reinterpret_cast<Smem*>(smraw);
    const int b = blockIdx.x >> 1;
    const uint32_t rank = blockIdx.x & 1;
    const uint32_t peer = rank ^ 1;
    const float* __restrict__ cpre_base = g_ctlpre + (size_t)b * Tn * 1024;

    // ---- zero recurrent state ----
    {
        float* p = &s->mem[0][0];
        for (int i = tid; i < Nn * Wn + Nn * Nn; i += NTH) p[i] = 0.f;
        if (tid < Wn) {
            s->c_ctl[tid] = 0.f; s->ww[tid] = 0.f;
            s->prec[0][tid] = 0.f; s->usage[tid] = 0.f; s->nrm[tid] = 0.f;
        }
        if (tid < 640) s->xs[tid] = 0.f;
        if (tid < 512) s->rw[tid] = 0.f;
        for (int i = tid; i < 2560; i += NTH) s->gp[6144 + i] = 0.f;  // h-partials (exact: h0=0)
    }
    __syncthreads();

    for (int t = 0; t <= Tn; ++t) {
        // ===== A: gates+out GEMV, rv-part only (h-part precomputed in F of t-1) =====
        {
            const int u = tid & 127, kc = tid >> 7;
            const uint2* wp = ((const uint2*)g_cboH) + u;
            const float* xsrc = s->xs;
            float4 a0 = make_float4(0, 0, 0, 0), a1 = a0;
            const int k0 = (int)rank * 256 + kc * 32;
#pragma unroll
            for (int kk = 0; kk < 32; kk += 4) GEMV_BLKH(wp, 160, k0 + kk);
            ((float4*)s->gp)[kc * 128 + u] =
                make_float4(a0.x + a1.x, a0.y + a1.y, a0.z + a1.z, a0.w + a1.w);
            if (tid < 512) {
                const int u2 = tid & 31, kc2 = tid >> 5;
                const uint2* wp2 = ((const uint2*)g_cboH) + 128 + u2;
                float4 b0 = make_float4(0, 0, 0, 0), b1 = b0;
                const int k0o = (int)rank * 256 + kc2 * 16;
#pragma unroll
                for (int kk = 0; kk < 16; kk += 2) {
                    float2 xv2 = *(const float2*)&xsrc[k0o + kk];
                    float4 w0 = h4tof4(wp2[(size_t)(k0o + kk) * 160]);
                    float4 w1 = h4tof4(wp2[(size_t)(k0o + kk + 1) * 160]);
                    b0.x += xv2.x * w0.x; b0.y += xv2.x * w0.y; b0.z += xv2.x * w0.z; b0.w += xv2.x * w0.w;
                    b1.x += xv2.y * w1.x; b1.y += xv2.y * w1.y; b1.z += xv2.y * w1.z; b1.w += xv2.y * w1.w;
                }
                ((float4*)s->gp)[1024 + kc2 * 32 + u2] =
                    make_float4(b0.x + b1.x, b0.y + b1.y, b0.z + b1.z, b0.w + b1.w);
            }
        }
        __syncthreads();
        // ===== reduce (rv + precomputed h partials) + exchange; warp 30 spins for encoder =====
        if (tid < 512) {
            float p = 0.f;
#pragma unroll
            for (int kc = 0; kc < 8; ++kc) p += s->gp[kc * 512 + tid];
#pragma unroll
            for (int c = 0; c < 4; ++c) p += s->gp[6144 + c * 512 + tid];
            s->bufo[tid] = p;
            dsmem_store(&s->pc[tid], peer, p);
        } else if (tid < 640) {
            const int o = tid - 512;
            float p = 0.f;
#pragma unroll
            for (int kc = 0; kc < 16; ++kc) p += s->gp[4096 + kc * 128 + o];
#pragma unroll
            for (int c = 0; c < 4; ++c) p += s->gp[8192 + c * 128 + o];
            s->bufo[tid] = p;
            dsmem_store(&s->pc[tid], peer, p);
        } else if (wid == 30 && lane == 0 && t < Tn) {
            while (ld_acquire(&g_prog[2 * b]) < t + 1 ||
                   ld_acquire(&g_prog[2 * b + 1]) < t + 1)
                __nanosleep(64);
        }
        CLUSTER_SYNC();
        // out row t-1
        if (t > 0 && rank == 0 && tid >= 512 && tid < 640)
            out[((size_t)b * Tn + (t - 1)) * Wn + (tid - 512)] =
                s->bufo[tid] + s->pc[tid] + g_bout[tid - 512];
        if (t == Tn) break;
        const int pcur = t & 1, pnxt = pcur ^ 1;
        // ctl cell
        if (tid < Wn) {
            const float* cp = cpre_base + (size_t)t * 1024;
            float gi = s->bufo[tid]       + s->pc[tid]       + __ldcg(cp + tid)       + __ldcg(cp + 512 + tid) + g_bctl[tid];
            float gf = s->bufo[128 + tid] + s->pc[128 + tid] + __ldcg(cp + 128 + tid) + __ldcg(cp + 640 + tid) + g_bctl[128 + tid];
            float gg = s->bufo[256 + tid] + s->pc[256 + tid] + __ldcg(cp + 256 + tid) + __ldcg(cp + 768 + tid) + g_bctl[256 + tid];
            float go = s->bufo[384 + tid] + s->pc[384 + tid] + __ldcg(cp + 384 + tid) + __ldcg(cp + 896 + tid) + g_bctl[384 + tid];
            gi = sigm(gi); gf = sigm(gf); gg = tanhf(gg); go = sigm(go);
            float c = gf * s->c_ctl[tid] + gi * gg;
            s->c_ctl[tid] = c;
            s->xs[512 + tid] = go * tanhf(c);
        }
        __syncthreads();

        // ===== iface GEMV (fp16 weights) =====
        if (tid < 920) {
            const int kc = tid / 230, u = tid - kc * 230;
            const uint2* wp = ((const uint2*)g_ifcH) + u;
            const float* xsrc = s->xs + 512;
            float4 a0 = make_float4(0, 0, 0, 0), a1 = a0;
            const int k0 = (int)rank * 64 + kc * 16;
#pragma unroll
            for (int kk = 0; kk < 16; kk += 4) GEMV_BLKH(wp, 230, k0 + kk);
            ((float4*)(s->gp + kc * 920))[u] =
                make_float4(a0.x + a1.x, a0.y + a1.y, a0.z + a1.z, a0.w + a1.w);
        }
        __syncthreads();
        if (tid < 920) {
            float p = s->gp[tid] + s->gp[920 + tid] + s->gp[1840 + tid] + s->gp[2760 + tid];
            s->bufo[tid] = p;
            dsmem_store(&s->pi[tid], peer, p);
        }
        CLUSTER_SYNC();

        // ===== D+E fused: {usage+uu (w0-3)} || {parse (w4-11)} || {mem.wk dots, wk inline (w16-31)} =====
        if (wid < 4) {
            float fgv = 0.f;
            if (lane < 4) fgv = sigm(s->bufo[901 + lane] + s->pi[901 + lane] + g_bifc[901 + lane]);
            float fg0 = __shfl_sync(0xffffffffu, fgv, 0);
            float fg1 = __shfl_sync(0xffffffffu, fgv, 1);
            float fg2 = __shfl_sync(0xffffffffu, fgv, 2);
            float fg3 = __shfl_sync(0xffffffffu, fgv, 3);
            float us = s->usage[tid];
            us = us + (1.f - us) * s->ww[tid];
            float ret = (1.f - fg0 * s->rw[tid])
                      * (1.f - fg1 * s->rw[Nn + tid])
                      * (1.f - fg2 * s->rw[2 * Nn + tid])
                      * (1.f - fg3 * s->rw[3 * Nn + tid]);
            us *= ret;
            s->usage[tid] = us;
            s->uu[tid] = DELTAf + (1.f - DELTAf) * us;
        } else if (wid < 12) {
            const int base = tid - 128;
#pragma unroll
            for (int q = 0; q < 4; ++q) {
                int j = base + 256 * q;
                if (j >= IFACEn) break;
                float v = s->bufo[j] + s->pi[j] + g_bifc[j];
                if (j < 512)       ((float*)s->rk)[j] = tanhf(v);
                else if (j < 516)  s->rstr[j - 512] = softplusf(v);
                else if (j == 644) s->scal[0] = softplusf(v);
                else if (j >= 645 && j < 773) s->er[j - 645] = sigm(v);
                else if (j >= 773 && j < 901) s->wv[j - 773] = tanhf(v);
                else if (j == 905) s->scal[1] = sigm(v);
                else if (j == 906) s->scal[2] = sigm(v);
                else if (j >= 907) s->xmraw[j - 907] = v;
            }
        } else if (wid >= 16) {
            const int o = 516 + lane * 4;
            float4 bf = *(const float4*)&s->bufo[o];
            float4 pf = *(const float4*)&s->pi[o];
            float4 gf4 = *(const float4*)&g_bifc[o];
            float4 k4 = make_float4(tanhf(bf.x + pf.x + gf4.x), tanhf(bf.y + pf.y + gf4.y),
                                    tanhf(bf.z + pf.z + gf4.z), tanhf(bf.w + pf.w + gf4.w));
            if (wid == 16) {
                float nv = wsum(dot4(k4, k4));
                if (lane == 0) s->scal[3] = sqrtf(nv);
            }
            const int n0 = (wid - 16) * 8;
#pragma unroll
            for (int rr = 0; rr < 8; ++rr) {
                int n = n0 + rr;
                float4 m4 = ((const float4*)s->mem[n])[lane];
                float dk = wsum(dot4(m4, k4));
                if (lane == 0) s->wc[n] = dk;
            }
        }
        __syncthreads();

        // ===== F: {rank+scan+alloc+ww (w0-3)} || {wc softmax (w8)} || {rm (w5)} || {rknorm (w12-15)}
        //        || {next-A gate-h prefetch (w16-31)} || {next-A out-h prefetch (w4,6,7,9)} =====
        if (tid < Nn) {
            float un = s->uu[tid];
            const float4* uu4 = (const float4*)s->uu;
            int rk_ = 0;
#pragma unroll 8
            for (int j4 = 0; j4 < 32; ++j4) {
                float4 u4 = uu4[j4];
                int j = j4 * 4;
                rk_ += (u4.x < un) || (u4.x == un && j + 0 < tid);
                rk_ += (u4.y < un) || (u4.y == un && j + 1 < tid);
                rk_ += (u4.z < un) || (u4.z == un && j + 2 < tid);
                rk_ += (u4.w < un) || (u4.w == un && j + 3 < tid);
            }
            s->rnk[tid] = rk_;
            s->psu[rk_] = un;
            asm volatile("bar.sync 1, 128;" ::: "memory");
            if (wid == 0) {
                float v0 = s->psu[lane * 4], v1 = s->psu[lane * 4 + 1];
                float v2 = s->psu[lane * 4 + 2], v3 = s->psu[lane * 4 + 3];
                float l1 = v0 * v1, l2 = l1 * v2, l3 = l2 * v3;
                float run = l3;
#pragma unroll
                for (int off = 1; off < 32; off <<= 1) {
                    float up = __shfl_up_sync(0xffffffffu, run, off);
                    if (lane >= off) run *= up;
                }
                float ex = __shfl_up_sync(0xffffffffu, run, 1);
                if (lane == 0) ex = 1.f;
                s->psu[lane * 4]     = ex * v0;
                s->psu[lane * 4 + 1] = ex * l1;
                s->psu[lane * 4 + 2] = ex * l2;
                s->psu[lane * 4 + 3] = ex * l3;
            }
            asm volatile("bar.sync 1, 128;" ::: "memory");
            asm volatile("bar.sync 2, 160;" ::: "memory");
            {
                int r_ = s->rnk[tid];
                float excl = (r_ == 0) ? 1.f : s->psu[r_ - 1];
                float alloc = (1.f - s->uu[tid]) * excl;
                float ag = s->scal[1], wg = s->scal[2];
                float v = wg * (ag * alloc + (1.f - ag) * s->wc[tid]);
                s->ww[tid] = v;
                float sm = wsum(v);
                if (lane == 0) s->red[wid] = sm;
            }
        } else if (wid == 8) {
            float inw = 1.f / ((s->scal[3] + DELTAf));
            float ws = s->scal[0];
            float v[4];
            float mx = -1e30f;
#pragma unroll
            for (int q = 0; q < 4; ++q) {
                int n = lane + 32 * q;
                v[q] = s->wc[n] / (s->nrm[n] + DELTAf) * inw * ws;
                mx = fmaxf(mx, v[q]);
            }
            mx = wmax(mx);
            float sm = 0.f;
#pragma unroll
            for (int q = 0; q < 4; ++q) { v[q] = expf(v[q] - mx); sm += v[q]; }
            sm = wsum(sm);
            float inv = 1.f / sm;
#pragma unroll
            for (int q = 0; q < 4; ++q) s->wc[lane + 32 * q] = v[q] * inv;
            asm volatile("bar.sync 2, 160;" ::: "memory");
        } else if (wid == 5 && lane < Rn) {
            int r = lane;
            float a = s->xmraw[r * 3], b2 = s->xmraw[r * 3 + 1], c2 = s->xmraw[r * 3 + 2];
            float m = fmaxf(a, fmaxf(b2, c2));
            float ea = expf(a - m), eb = expf(b2 - m), ec = expf(c2 - m);
            float inv = 1.f / (ea + eb + ec);
            s->rm[r][0] = ea * inv; s->rm[r][1] = eb * inv; s->rm[r][2] = ec * inv;
        } else if (wid >= 12 && wid < 12 + Rn) {
            int r = wid - 12;
            float4 k4 = ((const float4*)s->rk[r])[lane];
            float nv = wsum(dot4(k4, k4));
            if (lane == 0) s->rknorm[r] = sqrtf(nv);
        } else if (wid >= 16) {
            // gate-h prefetch for A(t+1): fp16 weights
            const int idx = tid - 512;
            const int u = idx & 127, c = idx >> 7;
            const uint2* wp = ((const uint2*)g_cboH) + u;
            const float* xsrc = s->xs;
            float4 a0 = make_float4(0, 0, 0, 0), a1 = a0;
            const int k0h = 512 + (int)rank * 64 + c * 16;
#pragma unroll
            for (int kk = 0; kk < 16; kk += 4) GEMV_BLKH(wp, 160, k0h + kk);
            ((float4*)s->gp)[1536 + c * 128 + u] =
                make_float4(a0.x + a1.x, a0.y + a1.y, a0.z + a1.z, a0.w + a1.w);
        } else if (wid == 4 || wid == 6 || wid == 7 || wid == 9) {
            // out-h prefetch: fp16 weights
            const int wmap = (wid == 4) ? 0 : (wid == 6) ? 1 : (wid == 7) ? 2 : 3;
            const int idx2 = wmap * 32 + lane;
            const int u2 = idx2 & 31, c2 = idx2 >> 5;
            const uint2* wp2 = ((const uint2*)g_cboH) + 128 + u2;
            const float* xsrc = s->xs;
            float4 b0 = make_float4(0, 0, 0, 0), b1 = b0;
            const int k0h = 512 + (int)rank * 64 + c2 * 16;
#pragma unroll
            for (int kk = 0; kk < 16; kk += 2) {
                float2 xv2 = *(const float2*)&xsrc[k0h + kk];
                float4 w0 = h4tof4(wp2[(size_t)(k0h + kk) * 160]);
                float4 w1 = h4tof4(wp2[(size_t)(k0h + kk + 1) * 160]);
                b0.x += xv2.x * w0.x; b0.y += xv2.x * w0.y; b0.z += xv2.x * w0.z; b0.w += xv2.x * w0.w;
                b1.x += xv2.y * w1.x; b1.y += xv2.y * w1.y; b1.z += xv2.y * w1.z; b1.w += xv2.y * w1.w;
            }
            ((float4*)s->gp)[2048 + c2 * 32 + u2] =
                make_float4(b0.x + b1.x, b0.y + b1.y, b0.z + b1.z, b0.w + b1.w);
        }
        __syncthreads();

        // ===== G: mem erase+write fused with new-mem dots; link update; prec =====
        {
            float4 k0 = ((const float4*)s->rk[0])[lane];
            float4 k1 = ((const float4*)s->rk[1])[lane];
            float4 k2 = ((const float4*)s->rk[2])[lane];
            float4 k3 = ((const float4*)s->rk[3])[lane];
            float4* m4 = (float4*)s->mem;
            float4 e = ((const float4*)s->er)[lane], v = ((const float4*)s->wv)[lane];
#pragma unroll
            for (int it = 0; it < 4; ++it) {
                int idx = tid + it * NTH;
                int n = wid + it * 32;
                float wwn = s->ww[n];
                float4 m = m4[idx];
                m.x = m.x * (1.f - wwn * e.x) + wwn * v.x;
                m.y = m.y * (1.f - wwn * e.y) + wwn * v.y;
                m.z = m.z * (1.f - wwn * e.z) + wwn * v.z;
                m.w = m.w * (1.f - wwn * e.w) + wwn * v.w;
                m4[idx] = m;
                float dn = wsum(dot4(m, m));
                float d0 = wsum(dot4(m, k0));
                float d1 = wsum(dot4(m, k1));
                float d2 = wsum(dot4(m, k2));
                float d3 = wsum(dot4(m, k3));
                if (lane == 0) {
                    s->nrm[n] = sqrtf(dn);
                    s->rc[0][n] = d0; s->rc[1][n] = d1; s->rc[2][n] = d2; s->rc[3][n] = d3;
                }
            }
            float4* l4 = (float4*)s->lnk;
            const float4* wwp = (const float4*)s->ww;
            const float4* pcp = (const float4*)s->prec[pcur];
#pragma unroll
            for (int it = 0; it < 4; ++it) {
                int idx = tid + it * NTH;
                int i = idx >> 5, q = idx & 31;
                float wwi = s->ww[i];
                float4 L = l4[idx], wj = wwp[q], pj = pcp[q];
                L.x = (1.f - wwi - wj.x) * L.x + wwi * pj.x;
                L.y = (1.f - wwi - wj.y) * L.y + wwi * pj.y;
                L.z = (1.f - wwi - wj.z) * L.z + wwi * pj.z;
                L.w = (1.f - wwi - wj.w) * L.w + wwi * pj.w;
                if ((i >> 2) == q) ((float*)&L)[i & 3] = 0.f;
                l4[idx] = L;
            }
            if (wid == 31) {
                float vv = (lane < 4) ? s->red[lane] : 0.f;
                float sw = wsum(vv);
#pragma unroll
                for (int q = 0; q < 4; ++q) {
                    int n = lane + 32 * q;
                    s->prec[pnxt][n] = (1.f - sw) * s->prec[pcur][n] + s->ww[n];
                }
            }
        }
        __syncthreads();

        // ===== H: {read softmax (w0-3)} || {bw col-acc all-r (w4-7)} || {fw row-dots (w8-31)} =====
        if (wid < Rn) {
            int r_ = wid;
            float inv_kn = 1.f / (s->rknorm[r_] + DELTAf);
            float rs = s->rstr[r_];
            float v[4];
            float mx = -1e30f;
#pragma unroll
            for (int q = 0; q < 4; ++q) {
                int n = lane + 32 * q;
                v[q] = s->rc[r_][n] / (s->nrm[n] + DELTAf) * inv_kn * rs;
                mx = fmaxf(mx, v[q]);
            }
            mx = wmax(mx);
            float sm = 0.f;
#pragma unroll
            for (int q = 0; q < 4; ++q) { v[q] = expf(v[q] - mx); sm += v[q]; }
            sm = wsum(sm);
            float inv = 1.f / sm;
#pragma unroll
            for (int q = 0; q < 4; ++q) s->rc[r_][lane + 32 * q] = v[q] * inv;
        } else if (wid < 8) {
            const int i = (wid - 4) * 32 + lane;
            const float4* rwA = (const float4*)(s->rw);
            const float4* rwB = (const float4*)(s->rw + Nn);
            const float4* rwC = (const float4*)(s->rw + 2 * Nn);
            const float4* rwD = (const float4*)(s->rw + 3 * Nn);
            float a0 = 0.f, a1 = 0.f, a2 = 0.f, a3 = 0.f;
#pragma unroll 4
            for (int j4 = 0; j4 < 32; ++j4) {
                float4 wA = rwA[j4], wB = rwB[j4], wC = rwC[j4], wD = rwD[j4];
                int j = j4 * 4;
                float L0 = s->lnk[j][i], L1 = s->lnk[j + 1][i];
                float L2 = s->lnk[j + 2][i], L3 = s->lnk[j + 3][i];
                a0 += wA.x * L0 + wA.y * L1 + wA.z * L2 + wA.w * L3;
                a1 += wB.x * L0 + wB.y * L1 + wB.z * L2 + wB.w * L3;
                a2 += wC.x * L0 + wC.y * L1 + wC.z * L2 + wC.w * L3;
                a3 += wD.x * L0 + wD.y * L1 + wD.z * L2 + wD.w * L3;
            }
            s->bwv[0][i] = a0; s->bwv[1][i] = a1; s->bwv[2][i] = a2; s->bwv[3][i] = a3;
        } else {
            float4 w0 = ((const float4*)s->rw)[lane];
            float4 w1 = ((const float4*)s->rw)[32 + lane];
            float4 w2 = ((const float4*)s->rw)[64 + lane];
            float4 w3 = ((const float4*)s->rw)[96 + lane];
            for (int i = wid - 8; i < Nn; i += 24) {
                float4 L = ((const float4*)s->lnk[i])[lane];
                float d0 = wsum(dot4(L, w0));
                float d1 = wsum(dot4(L, w1));
                float d2 = wsum(dot4(L, w2));
                float d3 = wsum(dot4(L, w3));
                if (lane == 0) {
                    s->fwv[0][i] = d0; s->fwv[1][i] = d1;
                    s->fwv[2][i] = d2; s->fwv[3][i] = d3;
                }
            }
        }
        __syncthreads();

        // ===== I1: rwn combine + commit rw =====
        if (tid < 512) {
            const int r_ = tid >> 7, i = tid & 127;
            float val = s->rm[r_][0] * s->bwv[r_][i]
                      + s->rm[r_][1] * s->fwv[r_][i]
                      + s->rm[r_][2] * s->rc[r_][i];
            s->rwn[tid] = val;
            s->rw[tid] = val;
        }
        __syncthreads();

        // ===== I2: rv direct (4 warps, all-r, float4 broadcasts + float4 store) =====
        if (wid < 4) {
            const int wcol = wid * 32 + lane;
            const float4* rnA = (const float4*)(s->rwn);
            const float4* rnB = (const float4*)(s->rwn + Nn);
            const float4* rnC = (const float4*)(s->rwn + 2 * Nn);
            const float4* rnD = (const float4*)(s->rwn + 3 * Nn);
            float a0 = 0.f, a1 = 0.f, a2 = 0.f, a3 = 0.f;
#pragma unroll 4
            for (int n4 = 0; n4 < 32; ++n4) {
                float4 wA = rnA[n4], wB = rnB[n4], wC = rnC[n4], wD = rnD[n4];
                int n = n4 * 4;
                float M0 = s->mem[n][wcol], M1 = s->mem[n + 1][wcol];
                float M2 = s->mem[n + 2][wcol], M3 = s->mem[n + 3][wcol];
                a0 += wA.x * M0 + wA.y * M1 + wA.z * M2 + wA.w * M3;
                a1 += wB.x * M0 + wB.y * M1 + wB.z * M2 + wB.w * M3;
                a2 += wC.x * M0 + wC.y * M1 + wC.z * M2 + wC.w * M3;
                a3 += wD.x * M0 + wD.y * M1 + wD.z * M2 + wD.w * M3;
            }
            ((float4*)s->xs)[wcol] = make_float4(a0, a1, a2, a3);
        }
        __syncthreads();
    }
}

extern "C" void kernel_launch(void* const* d_in, const int* in_sizes, int n_in,
                              void* d_out, int out_size) {
    const float* input   = (const float*)d_in[0];
    // d_in[1] = source_lengths (all == T, unused)
    const float* enc_Wih = (const float*)d_in[2];
    const float* enc_Whh = (const float*)d_in[3];
    const float* enc_bih = (const float*)d_in[4];
    const float* enc_bhh = (const float*)d_in[5];
    const float* ctl_Wih = (const float*)d_in[6];
    const float* ctl_Whh = (const float*)d_in[7];
    const float* ctl_bih = (const float*)d_in[8];
    const float* ctl_bhh = (const float*)d_in[9];
    const float* iface_W = (const float*)d_in[10];
    const float* iface_b = (const float*)d_in[11];
    const float* out_W   = (const float*)d_in[12];
    const float* out_b   = (const float*)d_in[13];
    float* out = (float*)d_out;

    prep_kernel<<<448, 256>>>(enc_Wih, enc_Whh, enc_bih, enc_bhh,
                              ctl_Wih, ctl_Whh, ctl_bih, ctl_bhh,
                              iface_W, iface_b, out_W, out_b);

    int smem = (int)sizeof(Smem);
    cudaFuncSetAttribute(dnc_kernel, cudaFuncAttributeMaxDynamicSharedMemorySize, smem);
    // 64 DNC + 64 encoder CTAs = 128 <= 148 SMs, occupancy 1/SM, all wave-1 resident;
    // producer/consumer spin (g_prog, reset by prep each launch) is deadlock-free.
    dnc_kernel<<<4 * Bn, NTH, smem>>>(input, out);
}

// round 17
// speedup vs baseline: 1.6522x; 1.6185x over previous
#include <cuda_runtime.h>
#include <cuda_fp16.h>
#include <cstddef>
#include <cstdint>

#define Bn 32
#define Tn 256
#define Wn 128
#define Rn 4
#define Nn 128
#define IFACEn 919
#define NTH 1024
#define DELTAf 1e-6f

typedef unsigned long long ull;

// -------- transposed-weight scratch + pipeline buffers (device globals) --------
__device__ float  g_encT[256 * 512];    // [k][j] fp32 (encoder, latency-hidden)
__device__ float  g_cpreT[128 * 512];   // [k][j] fp32
__device__ __half g_cboH[640 * 640];    // [k][j] fp16: k = rv(512)||h(128); j = gates(512)||out(128)
__device__ __half g_ifcH[128 * 920];    // [k][j] fp16, j padded 919->920
__device__ float  g_benc[512];
__device__ float  g_bctl[512];
__device__ float  g_bifc[920];
__device__ float  g_bout[128];
__device__ float  g_ctlpre[(size_t)Bn * Tn * 1024];
__device__ int    g_prog[2 * Bn];

__global__ void prep_kernel(
    const float* __restrict__ enc_Wih, const float* __restrict__ enc_Whh,
    const float* __restrict__ enc_bih, const float* __restrict__ enc_bhh,
    const float* __restrict__ ctl_Wih, const float* __restrict__ ctl_Whh,
    const float* __restrict__ ctl_bih, const float* __restrict__ ctl_bhh,
    const float* __restrict__ iface_W, const float* __restrict__ iface_b,
    const float* __restrict__ out_W, const float* __restrict__ out_b)
{
    const int idx = blockIdx.x * blockDim.x + threadIdx.x;
    const int stride = gridDim.x * blockDim.x;
    for (int i = idx; i < 256 * 512; i += stride) {
        int k = i >> 9, j = i & 511;
        g_encT[i] = (k < 128) ? enc_Wih[(size_t)j * 128 + k]
                              : enc_Whh[(size_t)j * 128 + (k - 128)];
    }
    for (int i = idx; i < 128 * 512; i += stride) {
        int k = i >> 9, j = i & 511;
        g_cpreT[i] = ctl_Wih[(size_t)j * 640 + 5 * k];
    }
    for (int i = idx; i < 640 * 640; i += stride) {
        int k = i / 640, j = i - k * 640;
        float v;
        if (j < 512) {
            v = (k < 512) ? ctl_Wih[(size_t)j * 640 + 5 * (k >> 2) + 1 + (k & 3)]
                          : ctl_Whh[(size_t)j * 128 + (k - 512)];
        } else {
            int o = j - 512;
            v = (k < 512) ? out_W[(size_t)o * 640 + 128 + k]
                          : out_W[(size_t)o * 640 + (k - 512)];
        }
        g_cboH[i] = __float2half_rn(v);
    }
    for (int i = idx; i < 128 * 920; i += stride) {
        int k = i / 920, j = i - k * 920;
        g_ifcH[i] = __float2half_rn((j < IFACEn) ? iface_W[(size_t)j * 128 + k] : 0.f);
    }
    if (idx < 512) {
        g_benc[idx] = enc_bih[idx] + enc_bhh[idx];
        g_bctl[idx] = ctl_bih[idx] + ctl_bhh[idx];
    }
    if (idx < 920) g_bifc[idx] = (idx < IFACEn) ? iface_b[idx] : 0.f;
    if (idx < 128) g_bout[idx] = out_b[idx];
    if (idx < 2 * Bn) g_prog[idx] = 0;   // reset pipeline flags EVERY launch
}

__device__ __forceinline__ float sigm(float x) { return 1.0f / (1.0f + expf(-x)); }
__device__ __forceinline__ float softplusf(float x) {
    return (x > 0.f) ? (x + log1pf(expf(-x))) : log1pf(expf(x));
}
__device__ __forceinline__ float wsum(float v) {
    v += __shfl_xor_sync(0xffffffffu, v, 16);
    v += __shfl_xor_sync(0xffffffffu, v, 8);
    v += __shfl_xor_sync(0xffffffffu, v, 4);
    v += __shfl_xor_sync(0xffffffffu, v, 2);
    v += __shfl_xor_sync(0xffffffffu, v, 1);
    return v;
}
__device__ __forceinline__ float wmax(float v) {
    v = fmaxf(v, __shfl_xor_sync(0xffffffffu, v, 16));
    v = fmaxf(v, __shfl_xor_sync(0xffffffffu, v, 8));
    v = fmaxf(v, __shfl_xor_sync(0xffffffffu, v, 4));
    v = fmaxf(v, __shfl_xor_sync(0xffffffffu, v, 2));
    v = fmaxf(v, __shfl_xor_sync(0xffffffffu, v, 1));
    return v;
}
__device__ __forceinline__ float dot4(float4 a, float4 b) {
    return a.x * b.x + a.y * b.y + a.z * b.z + a.w * b.w;
}
__device__ __forceinline__ void fma2(ull& acc, ull w, ull x) {
    asm("fma.rn.f32x2 %0, %1, %2, %0;" : "+l"(acc) : "l"(w), "l"(x));
}
__device__ __forceinline__ ull packf2(float x) {
    ull r; asm("mov.b64 %0, {%1, %1};" : "=l"(r) : "f"(x)); return r;
}
__device__ __forceinline__ float2 unpackf2(ull v) {
    float2 r; asm("mov.b64 {%0, %1}, %2;" : "=f"(r.x), "=f"(r.y) : "l"(v)); return r;
}
__device__ __forceinline__ float4 comb4(ull aL0, ull aH0, ull aL1, ull aH1) {
    float2 l0 = unpackf2(aL0), h0 = unpackf2(aH0), l1 = unpackf2(aL1), h1 = unpackf2(aH1);
    return make_float4(l0.x + l1.x, l0.y + l1.y, h0.x + h1.x, h0.y + h1.y);
}
__device__ __forceinline__ float4 h4tof4(uint2 w) {
    __half2 lo = *(__half2*)&w.x, hi = *(__half2*)&w.y;
    float2 l = __half22float2(lo), h = __half22float2(hi);
    return make_float4(l.x, l.y, h.x, h.y);
}
__device__ __forceinline__ void dsmem_store(void* local_ptr, uint32_t peer, float v) {
    uint32_t la = (uint32_t)__cvta_generic_to_shared(local_ptr);
    uint32_t rem;
    asm volatile("mapa.shared::cluster.u32 %0, %1, %2;" : "=r"(rem) : "r"(la), "r"(peer));
    asm volatile("st.shared::cluster.f32 [%0], %1;" :: "r"(rem), "f"(v) : "memory");
}
__device__ __forceinline__ int ld_acquire(const int* p) {
    int v; asm volatile("ld.acquire.gpu.global.s32 %0, [%1];" : "=r"(v) : "l"(p)); return v;
}
__device__ __forceinline__ void st_release(int* p, int v) {
    asm volatile("st.release.gpu.global.s32 [%0], %1;" :: "l"(p), "r"(v));
}
#define CLUSTER_SYNC() do { \
    asm volatile("barrier.cluster.arrive.aligned;" ::: "memory"); \
    asm volatile("barrier.cluster.wait.aligned;" ::: "memory"); } while (0)

// fp32 GEMV block (encoder only)
#define GEMV_BLK2(WP, RS, K)                                                   \
    {                                                                          \
        float4 xv = *(const float4*)&xsrc[(K)];                                \
        ulonglong2 w0 = (WP)[(size_t)((K) + 0) * (RS)];                        \
        ulonglong2 w1 = (WP)[(size_t)((K) + 1) * (RS)];                        \
        ulonglong2 w2 = (WP)[(size_t)((K) + 2) * (RS)];                        \
        ulonglong2 w3 = (WP)[(size_t)((K) + 3) * (RS)];                        \
        ull x0 = packf2(xv.x), x1 = packf2(xv.y), x2 = packf2(xv.z), x3 = packf2(xv.w); \
        fma2(aL0, w0.x, x0); fma2(aH0, w0.y, x0);                              \
        fma2(aL1, w1.x, x1); fma2(aH1, w1.y, x1);                              \
        fma2(aL0, w2.x, x2); fma2(aH0, w2.y, x2);                              \
        fma2(aL1, w3.x, x3); fma2(aH1, w3.y, x3);                              \
    }

// fp16-weight GEMV block: 4 k's, 4 LDG.64 + converts, fp32 accumulate (a0,a1 float4)
#define GEMV_BLKH(WP, RS, K)                                                   \
    {                                                                          \
        float4 xv = *(const float4*)&xsrc[(K)];                                \
        float4 w0 = h4tof4((WP)[(size_t)((K) + 0) * (RS)]);                    \
        float4 w1 = h4tof4((WP)[(size_t)((K) + 1) * (RS)]);                    \
        float4 w2 = h4tof4((WP)[(size_t)((K) + 2) * (RS)]);                    \
        float4 w3 = h4tof4((WP)[(size_t)((K) + 3) * (RS)]);                    \
        a0.x += xv.x * w0.x; a0.y += xv.x * w0.y; a0.z += xv.x * w0.z; a0.w += xv.x * w0.w; \
        a1.x += xv.y * w1.x; a1.y += xv.y * w1.y; a1.z += xv.y * w1.z; a1.w += xv.y * w1.w; \
        a0.x += xv.z * w2.x; a0.y += xv.z * w2.y; a0.z += xv.z * w2.z; a0.w += xv.z * w2.w; \
        a1.x += xv.w * w3.x; a1.y += xv.w * w3.y; a1.z += xv.w * w3.z; a1.w += xv.w * w3.w; \
    }

// ===================== SMEM layouts =====================
struct EncSmem {
    float gp[4096];
    float xs[256];
    float bufo[512];
    float pe[2][512];
    float h[128], c[128];
};

struct Smem {
    float mem[Nn][Wn];     // 64KB
    float lnk[Nn][Nn];     // 64KB
    float gp[8704];        // [0,4096) gate-rv | [4096,6144) out-rv | [6144,8192) gate-h | [8192,8704) out-h
    float xs[640];         // [rv(512, w*4+r) | h_ctl(128)]
    float bufo[920];
    float pc[640];
    float pi[920];
    float c_ctl[Wn];
    float rw[Rn * Nn];
    float rwn[Rn * Nn];
    float ww[Nn];
    float prec[2][Nn];
    float usage[Nn];
    float rk[Rn][Wn];
    float er[Wn];
    float wv[Wn];
    float rstr[Rn];
    float rknorm[Rn];
    float rm[Rn][3];
    float xmraw[12];
    float wc[Nn];
    float uu[Nn];
    float psu[Nn];
    float nrm[Nn];         // persists across steps
    float rc[Rn][Nn];
    float fwv[Rn][Nn];
    float bwv[Rn][Nn];
    float red[32];
    float scal[8];
    int   rnk[Nn];
};

// ===================== merged kernel: 64 DNC CTAs + 64 enc CTAs =====================
__global__ void __launch_bounds__(NTH, 1) __cluster_dims__(2, 1, 1) dnc_kernel(
    const float* __restrict__ input,
    float* __restrict__ out)
{
    extern __shared__ char smraw[];
    const int tid = threadIdx.x;
    const int wid = tid >> 5;
    const int lane = tid & 31;

    // ================= ENCODER ROLE (CTAs 64..127) =================
    if (blockIdx.x >= 2 * Bn) {
        EncSmem* s = reinterpret_cast<EncSmem*>(smraw);
        const int b = (blockIdx.x - 2 * Bn) >> 1;
        const uint32_t rank = blockIdx.x & 1;
        const uint32_t peer = rank ^ 1;

        if (tid < 128) { s->h[tid] = 0.f; s->c[tid] = 0.f; }
        __syncthreads();

        for (int t = 0; t < Tn; ++t) {
            if (tid < 128) {
                s->xs[tid] = input[((size_t)b * Tn + t) * Wn + tid];
                s->xs[128 + tid] = s->h[tid];
            }
            __syncthreads();
            {
                const int u = tid & 127, kc = tid >> 7;
                const ulonglong2* wp = ((const ulonglong2*)g_encT) + u;
                const float* xsrc = s->xs;
                ull aL0 = 0, aH0 = 0, aL1 = 0, aH1 = 0;
                const int k0 = (int)rank * 128 + kc * 16;
#pragma unroll
                for (int kk = 0; kk < 16; kk += 4) GEMV_BLK2(wp, 128, k0 + kk);
                ((float4*)s->gp)[kc * 128 + u] = comb4(aL0, aH0, aL1, aH1);
            }
            __syncthreads();
            if (tid < 512) {
                float p = 0.f;
#pragma unroll
                for (int kc = 0; kc < 8; ++kc) p += s->gp[kc * 512 + tid];
                s->bufo[tid] = p;
                dsmem_store(&s->pe[t & 1][tid], peer, p);
            }
            CLUSTER_SYNC();
            if (tid < 128) {
                const float* pe = s->pe[t & 1];
                float gi = sigm(s->bufo[tid]       + pe[tid]       + g_benc[tid]);
                float gf = sigm(s->bufo[128 + tid] + pe[128 + tid] + g_benc[128 + tid]);
                float gg = tanhf(s->bufo[256 + tid] + pe[256 + tid] + g_benc[256 + tid]);
                float go = sigm(s->bufo[384 + tid] + pe[384 + tid] + g_benc[384 + tid]);
                float c = gf * s->c[tid] + gi * gg;
                s->c[tid] = c;
                s->h[tid] = go * tanhf(c);
            }
            __syncthreads();
            {
                const int u = tid & 127, kc = tid >> 7;
                const ulonglong2* wp = ((const ulonglong2*)g_cpreT) + u;
                const float* xsrc = s->h;
                ull aL0 = 0, aH0 = 0, aL1 = 0, aH1 = 0;
                const int k0 = (int)rank * 64 + kc * 8;
#pragma unroll
                for (int kk = 0; kk < 8; kk += 4) GEMV_BLK2(wp, 128, k0 + kk);
                ((float4*)s->gp)[kc * 128 + u] = comb4(aL0, aH0, aL1, aH1);
            }
            __syncthreads();
            if (tid < 512) {
                float p = 0.f;
#pragma unroll
                for (int kc = 0; kc < 8; ++kc) p += s->gp[kc * 512 + tid];
                g_ctlpre[((size_t)b * Tn + t) * 1024 + rank * 512 + tid] = p;
                __threadfence();
            }
            __syncthreads();
            if (tid == 0) st_release(&g_prog[2 * b + rank], t + 1);
            __syncthreads();
        }
        return;
    }

    // ================= DNC ROLE (CTAs 0..63) =================
    Smem* s = reinterpret_cast<Smem*>(smraw);
    const int b = blockIdx.x >> 1;
    const uint32_t rank = blockIdx.x & 1;
    const uint32_t peer = rank ^ 1;
    const float* __restrict__ cpre_base = g_ctlpre + (size_t)b * Tn * 1024;

    // ---- zero recurrent state ----
    {
        float* p = &s->mem[0][0];
        for (int i = tid; i < Nn * Wn + Nn * Nn; i += NTH) p[i] = 0.f;
        if (tid < Wn) {
            s->c_ctl[tid] = 0.f; s->ww[tid] = 0.f;
            s->prec[0][tid] = 0.f; s->usage[tid] = 0.f; s->nrm[tid] = 0.f;
        }
        if (tid < 640) s->xs[tid] = 0.f;
        if (tid < 512) s->rw[tid] = 0.f;
        for (int i = tid; i < 2560; i += NTH) s->gp[6144 + i] = 0.f;  // h-partials (exact: h0=0)
    }
    __syncthreads();

    for (int t = 0; t <= Tn; ++t) {
        // ===== A: gates+out GEMV, rv-part only (h-part precomputed in F of t-1) =====
        {
            const int u = tid & 127, kc = tid >> 7;
            const uint2* wp = ((const uint2*)g_cboH) + u;
            const float* xsrc = s->xs;
            float4 a0 = make_float4(0, 0, 0, 0), a1 = a0;
            const int k0 = (int)rank * 256 + kc * 32;
#pragma unroll
            for (int kk = 0; kk < 32; kk += 4) GEMV_BLKH(wp, 160, k0 + kk);
            ((float4*)s->gp)[kc * 128 + u] =
                make_float4(a0.x + a1.x, a0.y + a1.y, a0.z + a1.z, a0.w + a1.w);
            if (tid < 512) {
                const int u2 = tid & 31, kc2 = tid >> 5;
                const uint2* wp2 = ((const uint2*)g_cboH) + 128 + u2;
                float4 b0 = make_float4(0, 0, 0, 0), b1 = b0;
                const int k0o = (int)rank * 256 + kc2 * 16;
#pragma unroll
                for (int kk = 0; kk < 16; kk += 2) {
                    float2 xv2 = *(const float2*)&xsrc[k0o + kk];
                    float4 w0 = h4tof4(wp2[(size_t)(k0o + kk) * 160]);
                    float4 w1 = h4tof4(wp2[(size_t)(k0o + kk + 1) * 160]);
                    b0.x += xv2.x * w0.x; b0.y += xv2.x * w0.y; b0.z += xv2.x * w0.z; b0.w += xv2.x * w0.w;
                    b1.x += xv2.y * w1.x; b1.y += xv2.y * w1.y; b1.z += xv2.y * w1.z; b1.w += xv2.y * w1.w;
                }
                ((float4*)s->gp)[1024 + kc2 * 32 + u2] =
                    make_float4(b0.x + b1.x, b0.y + b1.y, b0.z + b1.z, b0.w + b1.w);
            }
        }
        __syncthreads();
        // ===== reduce (rv + precomputed h partials) + exchange; warp 30 spins for encoder =====
        if (tid < 512) {
            float p = 0.f;
#pragma unroll
            for (int kc = 0; kc < 8; ++kc) p += s->gp[kc * 512 + tid];
#pragma unroll
            for (int c = 0; c < 4; ++c) p += s->gp[6144 + c * 512 + tid];
            s->bufo[tid] = p;
            dsmem_store(&s->pc[tid], peer, p);
        } else if (tid < 640) {
            const int o = tid - 512;
            float p = 0.f;
#pragma unroll
            for (int kc = 0; kc < 16; ++kc) p += s->gp[4096 + kc * 128 + o];
#pragma unroll
            for (int c = 0; c < 4; ++c) p += s->gp[8192 + c * 128 + o];
            s->bufo[tid] = p;
            dsmem_store(&s->pc[tid], peer, p);
        } else if (wid == 30 && lane == 0 && t < Tn) {
            while (ld_acquire(&g_prog[2 * b]) < t + 1 ||
                   ld_acquire(&g_prog[2 * b + 1]) < t + 1)
                __nanosleep(64);
        }
        CLUSTER_SYNC();
        // out row t-1
        if (t > 0 && rank == 0 && tid >= 512 && tid < 640)
            out[((size_t)b * Tn + (t - 1)) * Wn + (tid - 512)] =
                s->bufo[tid] + s->pc[tid] + g_bout[tid - 512];
        if (t == Tn) break;
        const int pcur = t & 1, pnxt = pcur ^ 1;
        // ctl cell
        if (tid < Wn) {
            const float* cp = cpre_base + (size_t)t * 1024;
            float gi = s->bufo[tid]       + s->pc[tid]       + __ldcg(cp + tid)       + __ldcg(cp + 512 + tid) + g_bctl[tid];
            float gf = s->bufo[128 + tid] + s->pc[128 + tid] + __ldcg(cp + 128 + tid) + __ldcg(cp + 640 + tid) + g_bctl[128 + tid];
            float gg = s->bufo[256 + tid] + s->pc[256 + tid] + __ldcg(cp + 256 + tid) + __ldcg(cp + 768 + tid) + g_bctl[256 + tid];
            float go = s->bufo[384 + tid] + s->pc[384 + tid] + __ldcg(cp + 384 + tid) + __ldcg(cp + 896 + tid) + g_bctl[384 + tid];
            gi = sigm(gi); gf = sigm(gf); gg = tanhf(gg); go = sigm(go);
            float c = gf * s->c_ctl[tid] + gi * gg;
            s->c_ctl[tid] = c;
            s->xs[512 + tid] = go * tanhf(c);
        }
        __syncthreads();

        // ===== iface GEMV (fp16 weights) =====
        if (tid < 920) {
            const int kc = tid / 230, u = tid - kc * 230;
            const uint2* wp = ((const uint2*)g_ifcH) + u;
            const float* xsrc = s->xs + 512;
            float4 a0 = make_float4(0, 0, 0, 0), a1 = a0;
            const int k0 = (int)rank * 64 + kc * 16;
#pragma unroll
            for (int kk = 0; kk < 16; kk += 4) GEMV_BLKH(wp, 230, k0 + kk);
            ((float4*)(s->gp + kc * 920))[u] =
                make_float4(a0.x + a1.x, a0.y + a1.y, a0.z + a1.z, a0.w + a1.w);
        }
        __syncthreads();
        if (tid < 920) {
            float p = s->gp[tid] + s->gp[920 + tid] + s->gp[1840 + tid] + s->gp[2760 + tid];
            s->bufo[tid] = p;
            dsmem_store(&s->pi[tid], peer, p);
        }
        CLUSTER_SYNC();

        // ===== D+E fused: {usage+uu (w0-3)} || {parse (w4-11)} || {mem.wk dots, wk inline (w16-31)} =====
        if (wid < 4) {
            float fgv = 0.f;
            if (lane < 4) fgv = sigm(s->bufo[901 + lane] + s->pi[901 + lane] + g_bifc[901 + lane]);
            float fg0 = __shfl_sync(0xffffffffu, fgv, 0);
            float fg1 = __shfl_sync(0xffffffffu, fgv, 1);
            float fg2 = __shfl_sync(0xffffffffu, fgv, 2);
            float fg3 = __shfl_sync(0xffffffffu, fgv, 3);
            float us = s->usage[tid];
            us = us + (1.f - us) * s->ww[tid];
            float ret = (1.f - fg0 * s->rw[tid])
                      * (1.f - fg1 * s->rw[Nn + tid])
                      * (1.f - fg2 * s->rw[2 * Nn + tid])
                      * (1.f - fg3 * s->rw[3 * Nn + tid]);
            us *= ret;
            s->usage[tid] = us;
            s->uu[tid] = DELTAf + (1.f - DELTAf) * us;
        } else if (wid < 12) {
            const int base = tid - 128;
#pragma unroll
            for (int q = 0; q < 4; ++q) {
                int j = base + 256 * q;
                if (j >= IFACEn) break;
                float v = s->bufo[j] + s->pi[j] + g_bifc[j];
                if (j < 512)       ((float*)s->rk)[j] = tanhf(v);
                else if (j < 516)  s->rstr[j - 512] = softplusf(v);
                else if (j == 644) s->scal[0] = softplusf(v);
                else if (j >= 645 && j < 773) s->er[j - 645] = sigm(v);
                else if (j >= 773 && j < 901) s->wv[j - 773] = tanhf(v);
                else if (j == 905) s->scal[1] = sigm(v);
                else if (j == 906) s->scal[2] = sigm(v);
                else if (j >= 907) s->xmraw[j - 907] = v;
            }
        } else if (wid >= 16) {
            const int o = 516 + lane * 4;
            float4 bf = *(const float4*)&s->bufo[o];
            float4 pf = *(const float4*)&s->pi[o];
            float4 gf4 = *(const float4*)&g_bifc[o];
            float4 k4 = make_float4(tanhf(bf.x + pf.x + gf4.x), tanhf(bf.y + pf.y + gf4.y),
                                    tanhf(bf.z + pf.z + gf4.z), tanhf(bf.w + pf.w + gf4.w));
            if (wid == 16) {
                float nv = wsum(dot4(k4, k4));
                if (lane == 0) s->scal[3] = sqrtf(nv);
            }
            const int n0 = (wid - 16) * 8;
#pragma unroll
            for (int rr = 0; rr < 8; ++rr) {
                int n = n0 + rr;
                float4 m4 = ((const float4*)s->mem[n])[lane];
                float dk = wsum(dot4(m4, k4));
                if (lane == 0) s->wc[n] = dk;
            }
        }
        __syncthreads();

        // ===== F: {rank+scan+alloc+ww (w0-3)} || {wc softmax (w8)} || {rm (w5)} || {rknorm (w12-15)}
        //        || {next-A gate-h prefetch (w16-31)} || {next-A out-h prefetch (w4,6,7,9)} =====
        if (tid < Nn) {
            float un = s->uu[tid];
            const float4* uu4 = (const float4*)s->uu;
            int rk_ = 0;
#pragma unroll 8
            for (int j4 = 0; j4 < 32; ++j4) {
                float4 u4 = uu4[j4];
                int j = j4 * 4;
                rk_ += (u4.x < un) || (u4.x == un && j + 0 < tid);
                rk_ += (u4.y < un) || (u4.y == un && j + 1 < tid);
                rk_ += (u4.z < un) || (u4.z == un && j + 2 < tid);
                rk_ += (u4.w < un) || (u4.w == un && j + 3 < tid);
            }
            s->rnk[tid] = rk_;
            s->psu[rk_] = un;
            asm volatile("bar.sync 1, 128;" ::: "memory");
            if (wid == 0) {
                float v0 = s->psu[lane * 4], v1 = s->psu[lane * 4 + 1];
                float v2 = s->psu[lane * 4 + 2], v3 = s->psu[lane * 4 + 3];
                float l1 = v0 * v1, l2 = l1 * v2, l3 = l2 * v3;
                float run = l3;
#pragma unroll
                for (int off = 1; off < 32; off <<= 1) {
                    float up = __shfl_up_sync(0xffffffffu, run, off);
                    if (lane >= off) run *= up;
                }
                float ex = __shfl_up_sync(0xffffffffu, run, 1);
                if (lane == 0) ex = 1.f;
                s->psu[lane * 4]     = ex * v0;
                s->psu[lane * 4 + 1] = ex * l1;
                s->psu[lane * 4 + 2] = ex * l2;
                s->psu[lane * 4 + 3] = ex * l3;
            }
            asm volatile("bar.sync 1, 128;" ::: "memory");
            asm volatile("bar.sync 2, 160;" ::: "memory");
            {
                int r_ = s->rnk[tid];
                float excl = (r_ == 0) ? 1.f : s->psu[r_ - 1];
                float alloc = (1.f - s->uu[tid]) * excl;
                float ag = s->scal[1], wg = s->scal[2];
                float v = wg * (ag * alloc + (1.f - ag) * s->wc[tid]);
                s->ww[tid] = v;
                float sm = wsum(v);
                if (lane == 0) s->red[wid] = sm;
            }
        } else if (wid == 8) {
            float inw = 1.f / ((s->scal[3] + DELTAf));
            float ws = s->scal[0];
            float v[4];
            float mx = -1e30f;
#pragma unroll
            for (int q = 0; q < 4; ++q) {
                int n = lane + 32 * q;
                v[q] = s->wc[n] / (s->nrm[n] + DELTAf) * inw * ws;
                mx = fmaxf(mx, v[q]);
            }
            mx = wmax(mx);
            float sm = 0.f;
#pragma unroll
            for (int q = 0; q < 4; ++q) { v[q] = expf(v[q] - mx); sm += v[q]; }
            sm = wsum(sm);
            float inv = 1.f / sm;
#pragma unroll
            for (int q = 0; q < 4; ++q) s->wc[lane + 32 * q] = v[q] * inv;
            asm volatile("bar.sync 2, 160;" ::: "memory");
        } else if (wid == 5 && lane < Rn) {
            int r = lane;
            float a = s->xmraw[r * 3], b2 = s->xmraw[r * 3 + 1], c2 = s->xmraw[r * 3 + 2];
            float m = fmaxf(a, fmaxf(b2, c2));
            float ea = expf(a - m), eb = expf(b2 - m), ec = expf(c2 - m);
            float inv = 1.f / (ea + eb + ec);
            s->rm[r][0] = ea * inv; s->rm[r][1] = eb * inv; s->rm[r][2] = ec * inv;
        } else if (wid >= 12 && wid < 12 + Rn) {
            int r = wid - 12;
            float4 k4 = ((const float4*)s->rk[r])[lane];
            float nv = wsum(dot4(k4, k4));
            if (lane == 0) s->rknorm[r] = sqrtf(nv);
        } else if (wid >= 16) {
            // gate-h prefetch for A(t+1): fp16 weights
            const int idx = tid - 512;
            const int u = idx & 127, c = idx >> 7;
            const uint2* wp = ((const uint2*)g_cboH) + u;
            const float* xsrc = s->xs;
            float4 a0 = make_float4(0, 0, 0, 0), a1 = a0;
            const int k0h = 512 + (int)rank * 64 + c * 16;
#pragma unroll
            for (int kk = 0; kk < 16; kk += 4) GEMV_BLKH(wp, 160, k0h + kk);
            ((float4*)s->gp)[1536 + c * 128 + u] =
                make_float4(a0.x + a1.x, a0.y + a1.y, a0.z + a1.z, a0.w + a1.w);
        } else if (wid == 4 || wid == 6 || wid == 7 || wid == 9) {
            // out-h prefetch: fp16 weights
            const int wmap = (wid == 4) ? 0 : (wid == 6) ? 1 : (wid == 7) ? 2 : 3;
            const int idx2 = wmap * 32 + lane;
            const int u2 = idx2 & 31, c2 = idx2 >> 5;
            const uint2* wp2 = ((const uint2*)g_cboH) + 128 + u2;
            const float* xsrc = s->xs;
            float4 b0 = make_float4(0, 0, 0, 0), b1 = b0;
            const int k0h = 512 + (int)rank * 64 + c2 * 16;
#pragma unroll
            for (int kk = 0; kk < 16; kk += 2) {
                float2 xv2 = *(const float2*)&xsrc[k0h + kk];
                float4 w0 = h4tof4(wp2[(size_t)(k0h + kk) * 160]);
                float4 w1 = h4tof4(wp2[(size_t)(k0h + kk + 1) * 160]);
                b0.x += xv2.x * w0.x; b0.y += xv2.x * w0.y; b0.z += xv2.x * w0.z; b0.w += xv2.x * w0.w;
                b1.x += xv2.y * w1.x; b1.y += xv2.y * w1.y; b1.z += xv2.y * w1.z; b1.w += xv2.y * w1.w;
            }
            ((float4*)s->gp)[2048 + c2 * 32 + u2] =
                make_float4(b0.x + b1.x, b0.y + b1.y, b0.z + b1.z, b0.w + b1.w);
        }
        __syncthreads();

        // ===== G: mem erase+write fused with new-mem dots; link update; prec =====
        {
            float4 k0 = ((const float4*)s->rk[0])[lane];
            float4 k1 = ((const float4*)s->rk[1])[lane];
            float4 k2 = ((const float4*)s->rk[2])[lane];
            float4 k3 = ((const float4*)s->rk[3])[lane];
            float4* m4 = (float4*)s->mem;
            float4 e = ((const float4*)s->er)[lane], v = ((const float4*)s->wv)[lane];
#pragma unroll
            for (int it = 0; it < 4; ++it) {
                int idx = tid + it * NTH;
                int n = wid + it * 32;
                float wwn = s->ww[n];
                float4 m = m4[idx];
                m.x = m.x * (1.f - wwn * e.x) + wwn * v.x;
                m.y = m.y * (1.f - wwn * e.y) + wwn * v.y;
                m.z = m.z * (1.f - wwn * e.z) + wwn * v.z;
                m.w = m.w * (1.f - wwn * e.w) + wwn * v.w;
                m4[idx] = m;
                float dn = wsum(dot4(m, m));
                float d0 = wsum(dot4(m, k0));
                float d1 = wsum(dot4(m, k1));
                float d2 = wsum(dot4(m, k2));
                float d3 = wsum(dot4(m, k3));
                if (lane == 0) {
                    s->nrm[n] = sqrtf(dn);
                    s->rc[0][n] = d0; s->rc[1][n] = d1; s->rc[2][n] = d2; s->rc[3][n] = d3;
                }
            }
            float4* l4 = (float4*)s->lnk;
            const float4* wwp = (const float4*)s->ww;
            const float4* pcp = (const float4*)s->prec[pcur];
#pragma unroll
            for (int it = 0; it < 4; ++it) {
                int idx = tid + it * NTH;
                int i = idx >> 5, q = idx & 31;
                float wwi = s->ww[i];
                float4 L = l4[idx], wj = wwp[q], pj = pcp[q];
                L.x = (1.f - wwi - wj.x) * L.x + wwi * pj.x;
                L.y = (1.f - wwi - wj.y) * L.y + wwi * pj.y;
                L.z = (1.f - wwi - wj.z) * L.z + wwi * pj.z;
                L.w = (1.f - wwi - wj.w) * L.w + wwi * pj.w;
                if ((i >> 2) == q) ((float*)&L)[i & 3] = 0.f;
                l4[idx] = L;
            }
            if (wid == 31) {
                float vv = (lane < 4) ? s->red[lane] : 0.f;
                float sw = wsum(vv);
#pragma unroll
                for (int q = 0; q < 4; ++q) {
                    int n = lane + 32 * q;
                    s->prec[pnxt][n] = (1.f - sw) * s->prec[pcur][n] + s->ww[n];
                }
            }
        }
        __syncthreads();

        // ===== H: {read softmax (w0-3)} || {bw col-acc all-r (w4-7)} || {fw row-dots (w8-31)} =====
        if (wid < Rn) {
            int r_ = wid;
            float inv_kn = 1.f / (s->rknorm[r_] + DELTAf);
            float rs = s->rstr[r_];
            float v[4];
            float mx = -1e30f;
#pragma unroll
            for (int q = 0; q < 4; ++q) {
                int n = lane + 32 * q;
                v[q] = s->rc[r_][n] / (s->nrm[n] + DELTAf) * inv_kn * rs;
                mx = fmaxf(mx, v[q]);
            }
            mx = wmax(mx);
            float sm = 0.f;
#pragma unroll
            for (int q = 0; q < 4; ++q) { v[q] = expf(v[q] - mx); sm += v[q]; }
            sm = wsum(sm);
            float inv = 1.f / sm;
#pragma unroll
            for (int q = 0; q < 4; ++q) s->rc[r_][lane + 32 * q] = v[q] * inv;
        } else if (wid < 8) {
            const int i = (wid - 4) * 32 + lane;
            const float4* rwA = (const float4*)(s->rw);
            const float4* rwB = (const float4*)(s->rw + Nn);
            const float4* rwC = (const float4*)(s->rw + 2 * Nn);
            const float4* rwD = (const float4*)(s->rw + 3 * Nn);
            float a0 = 0.f, a1 = 0.f, a2 = 0.f, a3 = 0.f;
#pragma unroll 4
            for (int j4 = 0; j4 < 32; ++j4) {
                float4 wA = rwA[j4], wB = rwB[j4], wC = rwC[j4], wD = rwD[j4];
                int j = j4 * 4;
                float L0 = s->lnk[j][i], L1 = s->lnk[j + 1][i];
                float L2 = s->lnk[j + 2][i], L3 = s->lnk[j + 3][i];
                a0 += wA.x * L0 + wA.y * L1 + wA.z * L2 + wA.w * L3;
                a1 += wB.x * L0 + wB.y * L1 + wB.z * L2 + wB.w * L3;
                a2 += wC.x * L0 + wC.y * L1 + wC.z * L2 + wC.w * L3;
                a3 += wD.x * L0 + wD.y * L1 + wD.z * L2 + wD.w * L3;
            }
            s->bwv[0][i] = a0; s->bwv[1][i] = a1; s->bwv[2][i] = a2; s->bwv[3][i] = a3;
        } else {
            float4 w0 = ((const float4*)s->rw)[lane];
            float4 w1 = ((const float4*)s->rw)[32 + lane];
            float4 w2 = ((const float4*)s->rw)[64 + lane];
            float4 w3 = ((const float4*)s->rw)[96 + lane];
            for (int i = wid - 8; i < Nn; i += 24) {
                float4 L = ((const float4*)s->lnk[i])[lane];
                float d0 = wsum(dot4(L, w0));
                float d1 = wsum(dot4(L, w1));
                float d2 = wsum(dot4(L, w2));
                float d3 = wsum(dot4(L, w3));
                if (lane == 0) {
                    s->fwv[0][i] = d0; s->fwv[1][i] = d1;
                    s->fwv[2][i] = d2; s->fwv[3][i] = d3;
                }
            }
        }
        __syncthreads();

        // ===== I1: rwn combine + commit rw =====
        if (tid < 512) {
            const int r_ = tid >> 7, i = tid & 127;
            float val = s->rm[r_][0] * s->bwv[r_][i]
                      + s->rm[r_][1] * s->fwv[r_][i]
                      + s->rm[r_][2] * s->rc[r_][i];
            s->rwn[tid] = val;
            s->rw[tid] = val;
        }
        __syncthreads();

        // ===== I2: rv direct (4 warps, all-r, float4 broadcasts + float4 store) =====
        if (wid < 4) {
            const int wcol = wid * 32 + lane;
            const float4* rnA = (const float4*)(s->rwn);
            const float4* rnB = (const float4*)(s->rwn + Nn);
            const float4* rnC = (const float4*)(s->rwn + 2 * Nn);
            const float4* rnD = (const float4*)(s->rwn + 3 * Nn);
            float a0 = 0.f, a1 = 0.f, a2 = 0.f, a3 = 0.f;
#pragma unroll 4
            for (int n4 = 0; n4 < 32; ++n4) {
                float4 wA = rnA[n4], wB = rnB[n4], wC = rnC[n4], wD = rnD[n4];
                int n = n4 * 4;
                float M0 = s->mem[n][wcol], M1 = s->mem[n + 1][wcol];
                float M2 = s->mem[n + 2][wcol], M3 = s->mem[n + 3][wcol];
                a0 += wA.x * M0 + wA.y * M1 + wA.z * M2 + wA.w * M3;
                a1 += wB.x * M0 + wB.y * M1 + wB.z * M2 + wB.w * M3;
                a2 += wC.x * M0 + wC.y * M1 + wC.z * M2 + wC.w * M3;
                a3 += wD.x * M0 + wD.y * M1 + wD.z * M2 + wD.w * M3;
            }
            ((float4*)s->xs)[wcol] = make_float4(a0, a1, a2, a3);
        }
        __syncthreads();
    }
}

extern "C" void kernel_launch(void* const* d_in, const int* in_sizes, int n_in,
                              void* d_out, int out_size) {
    const float* input   = (const float*)d_in[0];
    // d_in[1] = source_lengths (all == T, unused)
    const float* enc_Wih = (const float*)d_in[2];
    const float* enc_Whh = (const float*)d_in[3];
    const float* enc_bih = (const float*)d_in[4];
    const float* enc_bhh = (const float*)d_in[5];
    const float* ctl_Wih = (const float*)d_in[6];
    const float* ctl_Whh = (const float*)d_in[7];
    const float* ctl_bih = (const float*)d_in[8];
    const float* ctl_bhh = (const float*)d_in[9];
    const float* iface_W = (const float*)d_in[10];
    const float* iface_b = (const float*)d_in[11];
    const float* out_W   = (const float*)d_in[12];
    const float* out_b   = (const float*)d_in[13];
    float* out = (float*)d_out;

    prep_kernel<<<448, 256>>>(enc_Wih, enc_Whh, enc_bih, enc_bhh,
                              ctl_Wih, ctl_Whh, ctl_bih, ctl_bhh,
                              iface_W, iface_b, out_W, out_b);

    int smem = (int)sizeof(Smem);
    cudaFuncSetAttribute(dnc_kernel, cudaFuncAttributeMaxDynamicSharedMemorySize, smem);
    // 64 DNC + 64 encoder CTAs = 128 <= 148 SMs, occupancy 1/SM, all wave-1 resident;
    // producer/consumer spin (g_prog, reset by prep each launch) is deadlock-free.
    dnc_kernel<<<4 * Bn, NTH, smem>>>(input, out);
}